// round 4
// baseline (speedup 1.0000x reference)
#include <cuda_runtime.h>
#include <math.h>
#include <float.h>
#include <stdint.h>

#define NROWS   8192
#define IN_DIM  256
#define DIM     128
#define KCODES  8192
#define MBOOK   8
#define EPSBN   1e-5f

// output layout: x_hat [8192,256] ++ res_s [8,8192,128] ++ ce_s [8,8192,128]
#define RES_OFF ((size_t)NROWS * IN_DIM)
#define CE_OFF  (RES_OFF + (size_t)MBOOK * NROWS * DIM)

// scratch (static device allocations only)
__device__ float g_h1[NROWS * 128];
__device__ float g_h2[NROWS * 256];
__device__ float g_ze[NROWS * DIM];
__device__ float g_di[NROWS * DIM];
__device__ float g_t1[NROWS * 256];
__device__ float g_t2[NROWS * 128];
__device__ float g_nn[MBOOK * KCODES];   // ||e||^2 (matching reference)

// packed fp32 pair FMA: d = a*b + d, lanewise
__device__ __forceinline__ void ffma2(unsigned long long& d,
                                      unsigned long long a,
                                      unsigned long long b)
{
    asm("fma.rn.f32x2 %0, %1, %2, %0;" : "+l"(d) : "l"(a), "l"(b));
}

// ---------------------------------------------------------------------------
// Generic tiled GEMM: C = act(bn(A[N,KD] @ W[KD,P] + bias))
// ---------------------------------------------------------------------------
template<int KD, int P, bool BN, bool RELU>
__global__ void __launch_bounds__(256) gemm_kernel(
    const float* __restrict__ A, const float* __restrict__ W,
    const float* __restrict__ bias,
    const float* __restrict__ gg, const float* __restrict__ be,
    const float* __restrict__ rm, const float* __restrict__ rv,
    float* __restrict__ C)
{
    __shared__ __align__(16) float As[16][68];
    __shared__ __align__(16) float Ws[16][68];
    const int tid = threadIdx.x;
    const int rid = tid >> 4, cid = tid & 15;
    const int row0 = blockIdx.y * 64, col0 = blockIdx.x * 64;
    float acc[4][4] = {};

    for (int k0 = 0; k0 < KD; k0 += 16) {
        __syncthreads();
        #pragma unroll
        for (int i = 0; i < 4; i++) {
            int idx = tid + i * 256;
            int r  = idx >> 4, kk  = idx & 15;
            As[kk][r] = A[(size_t)(row0 + r) * KD + (k0 + kk)];
            int kk2 = idx >> 6, c  = idx & 63;
            Ws[kk2][c] = W[(size_t)(k0 + kk2) * P + (col0 + c)];
        }
        __syncthreads();
        #pragma unroll
        for (int kk = 0; kk < 16; kk++) {
            float4 a = *(const float4*)&As[kk][rid * 4];
            float4 w = *(const float4*)&Ws[kk][cid * 4];
            float av[4] = {a.x, a.y, a.z, a.w};
            float wv[4] = {w.x, w.y, w.z, w.w};
            #pragma unroll
            for (int r = 0; r < 4; r++)
                #pragma unroll
                for (int c = 0; c < 4; c++)
                    acc[r][c] += av[r] * wv[c];
        }
    }
    #pragma unroll
    for (int r = 0; r < 4; r++) {
        int row = row0 + rid * 4 + r;
        #pragma unroll
        for (int c = 0; c < 4; c++) {
            int col = col0 + cid * 4 + c;
            float v = acc[r][c] + bias[col];
            if constexpr (BN)
                v = (v - rm[col]) / sqrtf(rv[col] + EPSBN) * gg[col] + be[col];
            if constexpr (RELU)
                v = fmaxf(v, 0.0f);
            C[(size_t)row * P + col] = v;
        }
    }
}

// ---------------------------------------------------------------------------
// ||E_k||^2 (split grid in half so vq_kernel lands on ncu's -s 5 slot)
// ---------------------------------------------------------------------------
__global__ void norm_kernel(const float* __restrict__ cbk, int base)
{
    int i = base + blockIdx.x * 256 + threadIdx.x;
    const float4* p = (const float4*)(cbk + (size_t)i * DIM);
    float s = 0.f;
    #pragma unroll
    for (int j = 0; j < DIM / 4; j++) {
        float4 q = p[j];
        s += q.x * q.x + q.y * q.y + q.z * q.z + q.w * q.w;
    }
    g_nn[i] = s;
}

// ---------------------------------------------------------------------------
// Residual VQ, v4: broadcast-codes layout.
//   warp w: 32 distinct rows (lane = row within half, half = w&1),
//           32-code slice per cb (slice = w>>1).
//   b-loads broadcast (16B unique), a-load 1/dq conflict-free -> FMA-bound.
//   E staged code-major (stride 33 16B-units) via cp.async, double buffered.
//   score: d = fmaf(-2, dot, rr) + ee  (== (rr - 2*dot) + ee bitwise)
// ---------------------------------------------------------------------------
#define VROWS 64
#define VCT   128
#define RES_STRIDE 132                     // floats per res row (33 16B units)
#define E_STRIDE_B 528                     // bytes per code (33 16B units)
#define ES_FLOATS  (VCT * 33 * 4)          // floats per E buffer

__device__ __forceinline__ void stageE(float* Ebuf, const float* __restrict__ Eb,
                                       int cb, int tid)
{
    #pragma unroll
    for (int v = 0; v < 16; v++) {
        int f    = v * 256 + tid;
        int code = f >> 5, dq = f & 31;
        int phys = code * 33 + dq;
        uint32_t dst = (uint32_t)__cvta_generic_to_shared(Ebuf + phys * 4);
        const float* src = Eb + ((size_t)(cb * VCT + code) << 7) + (dq << 2);
        asm volatile("cp.async.cg.shared.global [%0], [%1], 16;"
                     :: "r"(dst), "l"(src));
    }
    asm volatile("cp.async.commit_group;");
}

__global__ void __launch_bounds__(256, 1) vq_kernel(
    const float* __restrict__ ze, const float* __restrict__ cbk,
    float* __restrict__ out)
{
    extern __shared__ float sm[];
    float* res_t   = sm;                                   // [64][132]
    float* Esm     = sm + VROWS * RES_STRIDE;              // 2 x ES_FLOATS
    float* rr_s    = Esm + 2 * ES_FLOATS;                  // [64]
    float* redv    = rr_s + VROWS;                         // [8][32]
    int*   redi    = (int*)(redv + 256);                   // [8][32]
    int*   bestIdx = redi + 256;                           // [64]

    const int tid  = threadIdx.x;
    const int row0 = blockIdx.x * VROWS;
    const int warp = tid >> 5, lane = tid & 31;
    const int rh   = warp & 1;                // row half
    const int cg   = (warp >> 1) * 32;        // code slice within cb
    const int myrow = rh * 32 + lane;

    // residual := ze
    #pragma unroll
    for (int i = 0; i < 8; i++) {
        int g = tid + i * 256;
        int r = g >> 5, dq = g & 31;
        *(float4*)(res_t + r * RES_STRIDE + dq * 4) =
            *(const float4*)(ze + (size_t)(row0 + r) * DIM + dq * 4);
    }
    __syncthreads();

    for (int m = 0; m < MBOOK; m++) {
        const float* Eb = cbk + (size_t)m * KCODES * DIM;
        const float* nb = g_nn + m * KCODES;

        // kick off first E tile (overlaps emission + rr below)
        stageE(Esm, Eb, 0, tid);

        // emit res_s[m]
        {
            size_t ob = RES_OFF + (size_t)m * NROWS * DIM + (size_t)row0 * DIM;
            #pragma unroll
            for (int i = 0; i < 8; i++) {
                int g = tid + i * 256;
                int r = g >> 5, dq = g & 31;
                *(float4*)(out + ob + (size_t)r * DIM + dq * 4) =
                    *(const float4*)(res_t + r * RES_STRIDE + dq * 4);
            }
        }

        // per-row ||r||^2 (sequential dim order)
        if (tid < VROWS) {
            float s = 0.f;
            #pragma unroll
            for (int dq = 0; dq < 32; dq++) {
                float4 v = *(const float4*)(res_t + tid * RES_STRIDE + dq * 4);
                s = fmaf(v.x, v.x, s); s = fmaf(v.y, v.y, s);
                s = fmaf(v.z, v.z, s); s = fmaf(v.w, v.w, s);
            }
            rr_s[tid] = s;
        }
        __syncthreads();

        const float rr = rr_s[myrow];
        const float* myres = res_t + myrow * RES_STRIDE;

        float best = FLT_MAX;
        int   bidx = 0x7fffffff;

        int p = 0;
        for (int cb = 0; cb < KCODES / VCT; cb++) {
            if (cb < KCODES / VCT - 1) {
                stageE(Esm + (p ^ 1) * ES_FLOATS, Eb, cb + 1, tid);
                asm volatile("cp.async.wait_group 1;");
            } else {
                asm volatile("cp.async.wait_group 0;");
            }
            __syncthreads();

            const char* Ebase = (const char*)(Esm + p * ES_FLOATS)
                                + (size_t)cg * E_STRIDE_B;

            unsigned long long acc[32];
            #pragma unroll
            for (int c = 0; c < 32; c++) acc[c] = 0ull;

            #pragma unroll 4
            for (int dq = 0; dq < 32; dq++) {
                ulonglong2 a2 = *(const ulonglong2*)(myres + dq * 4);
                const char* Edq = Ebase + dq * 16;
                #pragma unroll
                for (int c = 0; c < 32; c++) {
                    ulonglong2 b2 = *(const ulonglong2*)(Edq + c * E_STRIDE_B);
                    ffma2(acc[c], a2.x, b2.x);
                    ffma2(acc[c], a2.y, b2.y);
                }
            }

            // scores: d = (rr - 2*dot) + ee  (reference rounding)
            const int code0 = cb * VCT + cg;
            #pragma unroll
            for (int c = 0; c < 32; c++) {
                unsigned long long a = acc[c];
                float dot = __uint_as_float((unsigned)(a & 0xffffffffull))
                          + __uint_as_float((unsigned)(a >> 32));
                float ee = __ldg(nb + code0 + c);
                float d  = fmaf(-2.0f, dot, rr) + ee;
                if (d < best) { best = d; bidx = code0 + c; }
            }
            __syncthreads();
            p ^= 1;
        }

        // cross-warp argmin reduce (4 code slices per row; tie -> lower idx)
        redv[warp * 32 + lane] = best;
        redi[warp * 32 + lane] = bidx;
        __syncthreads();
        if (warp < 2) {
            float b_ = redv[warp * 32 + lane];
            int   i_ = redi[warp * 32 + lane];
            #pragma unroll
            for (int k = 1; k < 4; k++) {
                float ob = redv[(warp + 2 * k) * 32 + lane];
                int   oi = redi[(warp + 2 * k) * 32 + lane];
                if (ob < b_ || (ob == b_ && oi < i_)) { b_ = ob; i_ = oi; }
            }
            bestIdx[warp * 32 + lane] = i_;
        }
        __syncthreads();

        // quantize: emit ce_s[m], residual -= ce
        #pragma unroll 1
        for (int rr2 = 0; rr2 < VROWS / 8; rr2++) {
            int row = warp * 8 + rr2;
            int idx = bestIdx[row];
            const float4* e = (const float4*)(Eb + (size_t)idx * DIM);
            size_t ob = CE_OFF + (size_t)m * NROWS * DIM + (size_t)(row0 + row) * DIM;
            float4 cv = __ldg(e + lane);
            *(float4*)(out + ob + lane * 4) = cv;
            float4* rp = (float4*)(res_t + row * RES_STRIDE + lane * 4);
            float4 rv = *rp;
            rv.x -= cv.x; rv.y -= cv.y; rv.z -= cv.z; rv.w -= cv.w;
            *rp = rv;
        }
        __syncthreads();
    }
}

// ---------------------------------------------------------------------------
// di = ze + (sum_m ce_s[m] - ze)
// ---------------------------------------------------------------------------
__global__ void di_kernel(const float* __restrict__ out)
{
    int i = blockIdx.x * 256 + threadIdx.x;
    float zev = g_ze[i];
    float zq = 0.f;
    #pragma unroll
    for (int m = 0; m < MBOOK; m++)
        zq += out[CE_OFF + (size_t)m * NROWS * DIM + i];
    g_di[i] = zev + (zq - zev);
}

// ---------------------------------------------------------------------------
extern "C" void kernel_launch(void* const* d_in, const int* in_sizes, int n_in,
                              void* d_out, int out_size)
{
    const float* x   = (const float*)d_in[0];
    const float* W1  = (const float*)d_in[1];
    const float* b1  = (const float*)d_in[2];
    const float* g1  = (const float*)d_in[3];
    const float* be1 = (const float*)d_in[4];
    const float* rm1 = (const float*)d_in[5];
    const float* rv1 = (const float*)d_in[6];
    const float* W2  = (const float*)d_in[7];
    const float* b2  = (const float*)d_in[8];
    const float* g2  = (const float*)d_in[9];
    const float* be2 = (const float*)d_in[10];
    const float* rm2 = (const float*)d_in[11];
    const float* rv2 = (const float*)d_in[12];
    const float* W3  = (const float*)d_in[13];
    const float* b3  = (const float*)d_in[14];
    const float* cbk = (const float*)d_in[15];
    const float* W4  = (const float*)d_in[16];
    const float* b4  = (const float*)d_in[17];
    const float* g3  = (const float*)d_in[18];
    const float* be3 = (const float*)d_in[19];
    const float* rm3 = (const float*)d_in[20];
    const float* rv3 = (const float*)d_in[21];
    const float* W5  = (const float*)d_in[22];
    const float* b5  = (const float*)d_in[23];
    const float* g4  = (const float*)d_in[24];
    const float* be4 = (const float*)d_in[25];
    const float* rm4 = (const float*)d_in[26];
    const float* rv4 = (const float*)d_in[27];
    const float* W6  = (const float*)d_in[28];
    const float* b6  = (const float*)d_in[29];
    float* out = (float*)d_out;

    float *h1, *h2, *ze, *di, *t1, *t2;
    cudaGetSymbolAddress((void**)&h1, g_h1);
    cudaGetSymbolAddress((void**)&h2, g_h2);
    cudaGetSymbolAddress((void**)&ze, g_ze);
    cudaGetSymbolAddress((void**)&di, g_di);
    cudaGetSymbolAddress((void**)&t1, g_t1);
    cudaGetSymbolAddress((void**)&t2, g_t2);

    const int VQ_SMEM = (VROWS * RES_STRIDE + 2 * ES_FLOATS + VROWS + 256) * 4
                        + 256 * 4 + VROWS * 4;
    cudaFuncSetAttribute(vq_kernel,
                         cudaFuncAttributeMaxDynamicSharedMemorySize, VQ_SMEM);

    // codebook norms (2 launches so vq_kernel is launch index 5 for ncu -s 5)
    norm_kernel<<<MBOOK * KCODES / 512, 256>>>(cbk, 0);
    norm_kernel<<<MBOOK * KCODES / 512, 256>>>(cbk, MBOOK * KCODES / 2);

    // encoder
    gemm_kernel<256, 128, true,  true ><<<dim3(2, 128), 256>>>(x,  W1, b1, g1, be1, rm1, rv1, h1);
    gemm_kernel<128, 256, true,  true ><<<dim3(4, 128), 256>>>(h1, W2, b2, g2, be2, rm2, rv2, h2);
    gemm_kernel<256, 128, false, false><<<dim3(2, 128), 256>>>(h2, W3, b3, nullptr, nullptr, nullptr, nullptr, ze);

    // residual VQ (launch index 5)
    vq_kernel<<<NROWS / VROWS, 256, VQ_SMEM>>>(ze, cbk, out);

    // straight-through: di = ze + (zq - ze)
    di_kernel<<<NROWS * DIM / 256, 256>>>(out);

    // decoder
    gemm_kernel<128, 256, true,  true ><<<dim3(4, 128), 256>>>(di, W4, b4, g3, be3, rm3, rv3, t1);
    gemm_kernel<256, 128, true,  true ><<<dim3(2, 128), 256>>>(t1, W5, b5, g4, be4, rm4, rv4, t2);
    gemm_kernel<128, 256, false, false><<<dim3(4, 128), 256>>>(t2, W6, b6, nullptr, nullptr, nullptr, nullptr, out);
}

// round 7
// speedup vs baseline: 2.4419x; 2.4419x over previous
#include <cuda_runtime.h>
#include <cuda_bf16.h>
#include <math.h>
#include <float.h>
#include <stdint.h>

#define NROWS   8192
#define IN_DIM  256
#define DIM     128
#define KCODES  8192
#define MBOOK   8
#define EPSBN   1e-5f

// output layout: x_hat [8192,256] ++ res_s [8,8192,128] ++ ce_s [8,8192,128]
#define RES_OFF ((size_t)NROWS * IN_DIM)
#define CE_OFF  (RES_OFF + (size_t)MBOOK * NROWS * DIM)

// scratch (static device allocations only)
__device__ float g_h1[NROWS * 128];
__device__ float g_h2[NROWS * 256];
__device__ float g_ze[NROWS * DIM];
__device__ float g_di[NROWS * DIM];
__device__ float g_t1[NROWS * 256];
__device__ float g_t2[NROWS * 128];
__device__ float g_nn[MBOOK * KCODES];                 // ||e||^2 fp32
__device__ __nv_bfloat16 g_cbh[MBOOK * KCODES * DIM];  // bf16 limb hi
__device__ __nv_bfloat16 g_cbm[MBOOK * KCODES * DIM];  // bf16 limb mid

// ---------------------------------------------------------------------------
// mma.sync / ldmatrix helpers (baseline PTX, compiles for compute_103)
// ---------------------------------------------------------------------------
#define MMA16816(d0,d1,d2,d3,a0,a1,a2,a3,b0,b1) \
    asm volatile("mma.sync.aligned.m16n8k16.row.col.f32.bf16.bf16.f32 " \
        "{%0,%1,%2,%3}, {%4,%5,%6,%7}, {%8,%9}, {%0,%1,%2,%3};" \
        : "+f"(d0), "+f"(d1), "+f"(d2), "+f"(d3) \
        : "r"(a0), "r"(a1), "r"(a2), "r"(a3), "r"(b0), "r"(b1))

#define LDSM4(r0,r1,r2,r3,addr) \
    asm volatile("ldmatrix.sync.aligned.m8n8.x4.shared.b16 {%0,%1,%2,%3}, [%4];" \
        : "=r"(r0), "=r"(r1), "=r"(r2), "=r"(r3) : "r"(addr))

__device__ __forceinline__ uint32_t smem_u32(const void* p) {
    uint32_t a;
    asm("{ .reg .u64 t; cvta.to.shared.u64 t, %1; cvt.u32.u64 %0, t; }"
        : "=r"(a) : "l"(p));
    return a;
}

__device__ __forceinline__ uint32_t pack_bf16(__nv_bfloat16 a, __nv_bfloat16 b) {
    return (uint32_t)__bfloat16_as_ushort(a)
         | ((uint32_t)__bfloat16_as_ushort(b) << 16);
}

// split float2 into 2 bf16x2 limbs (error ~2^-17 rel, absorbed by rescore)
__device__ __forceinline__ void split2(float2 v, uint32_t& h, uint32_t& m) {
    __nv_bfloat16 h0 = __float2bfloat16(v.x); float hf0 = __bfloat162float(h0);
    __nv_bfloat16 m0 = __float2bfloat16(v.x - hf0);
    __nv_bfloat16 h1 = __float2bfloat16(v.y); float hf1 = __bfloat162float(h1);
    __nv_bfloat16 m1 = __float2bfloat16(v.y - hf1);
    h = pack_bf16(h0, h1); m = pack_bf16(m0, m1);
}

// ---------------------------------------------------------------------------
// Generic tiled GEMM: C = act(bn(A[N,KD] @ W[KD,P] + bias))
// ---------------------------------------------------------------------------
template<int KD, int P, bool BN, bool RELU>
__global__ void __launch_bounds__(256) gemm_kernel(
    const float* __restrict__ A, const float* __restrict__ W,
    const float* __restrict__ bias,
    const float* __restrict__ gg, const float* __restrict__ be,
    const float* __restrict__ rm, const float* __restrict__ rv,
    float* __restrict__ C)
{
    __shared__ __align__(16) float As[16][68];
    __shared__ __align__(16) float Ws[16][68];
    const int tid = threadIdx.x;
    const int rid = tid >> 4, cid = tid & 15;
    const int row0 = blockIdx.y * 64, col0 = blockIdx.x * 64;
    float acc[4][4] = {};

    for (int k0 = 0; k0 < KD; k0 += 16) {
        __syncthreads();
        #pragma unroll
        for (int i = 0; i < 4; i++) {
            int idx = tid + i * 256;
            int r  = idx >> 4, kk  = idx & 15;
            As[kk][r] = A[(size_t)(row0 + r) * KD + (k0 + kk)];
            int kk2 = idx >> 6, c  = idx & 63;
            Ws[kk2][c] = W[(size_t)(k0 + kk2) * P + (col0 + c)];
        }
        __syncthreads();
        #pragma unroll
        for (int kk = 0; kk < 16; kk++) {
            float4 a = *(const float4*)&As[kk][rid * 4];
            float4 w = *(const float4*)&Ws[kk][cid * 4];
            float av[4] = {a.x, a.y, a.z, a.w};
            float wv[4] = {w.x, w.y, w.z, w.w};
            #pragma unroll
            for (int r = 0; r < 4; r++)
                #pragma unroll
                for (int c = 0; c < 4; c++)
                    acc[r][c] += av[r] * wv[c];
        }
    }
    #pragma unroll
    for (int r = 0; r < 4; r++) {
        int row = row0 + rid * 4 + r;
        #pragma unroll
        for (int c = 0; c < 4; c++) {
            int col = col0 + cid * 4 + c;
            float v = acc[r][c] + bias[col];
            if constexpr (BN)
                v = (v - rm[col]) / sqrtf(rv[col] + EPSBN) * gg[col] + be[col];
            if constexpr (RELU)
                v = fmaxf(v, 0.0f);
            C[(size_t)row * P + col] = v;
        }
    }
}

// ---------------------------------------------------------------------------
// codebook prep: ||e||^2 fp32 + bf16 2-limb split
// ---------------------------------------------------------------------------
__global__ void norm_kernel(const float* __restrict__ cbk)
{
    int i = blockIdx.x * 256 + threadIdx.x;
    const float4* p = (const float4*)(cbk + (size_t)i * DIM);
    float s = 0.f;
    #pragma unroll
    for (int j = 0; j < DIM / 4; j++) {
        float4 q = p[j];
        s += q.x * q.x + q.y * q.y + q.z * q.z + q.w * q.w;
    }
    g_nn[i] = s;
}

__global__ void split_kernel(const float* __restrict__ cbk)
{
    size_t i = (size_t)blockIdx.x * 256 + threadIdx.x;
    float v = cbk[i];
    __nv_bfloat16 h = __float2bfloat16(v);
    float hf = __bfloat162float(h);
    __nv_bfloat16 m = __float2bfloat16(v - hf);
    g_cbh[i] = h; g_cbm[i] = m;
}

// ---------------------------------------------------------------------------
// Residual VQ v7: mma.sync bf16 3-term approx scoring (hh,hm,mh)
//                 + per-thread top-2 capture + exact fp32 rescore.
//  CTA: 64 rows, 8 warps. warp = rowgroup(16 rows) x code-half(32 of 64-tile).
//  Rescore reproduces reference rounding: d = (rr - 2*dot_fp32) + ee.
// ---------------------------------------------------------------------------
#define VROWS 64
#define TC    64
#define NT    (KCODES / TC)
#define RES_STRIDE 132
#define EBUF_B (2 * TC * 256)             // 32768 bytes per buffer

// smem byte offsets
#define SM_RES  0                          // 64*132*4 = 33792
#define SM_RRS  33792                      // 64 floats
#define SM_CAND 34048                      // 64*16 ints = 4096
#define SM_BIDX 38144                      // 64 ints
#define SM_EBUF 38400                      // 2 * EBUF_B
#define SM_TOTAL (SM_EBUF + 2 * EBUF_B)    // 103936

__device__ __forceinline__ void stageE(uint32_t ebuf_sm,
                                       const __nv_bfloat16* __restrict__ bh,
                                       const __nv_bfloat16* __restrict__ bm,
                                       int tile, int tid)
{
    #pragma unroll
    for (int i = 0; i < 8; i++) {
        int ch = tid + i * 256;                   // 0..2047
        int limb = ch >> 10;
        int rem  = ch & 1023;
        int code = rem >> 4, g = rem & 15;
        const __nv_bfloat16* src = (limb == 0 ? bh : bm)
            + ((size_t)(tile * TC + code) << 7) + (g << 3);
        uint32_t dst = ebuf_sm + limb * (TC * 256) + code * 256
                     + ((g ^ (code & 7)) << 4);
        asm volatile("cp.async.cg.shared.global [%0], [%1], 16;"
                     :: "r"(dst), "l"(src));
    }
    asm volatile("cp.async.commit_group;");
}

__global__ void __launch_bounds__(256, 1) vq_kernel(
    const float* __restrict__ ze, const float* __restrict__ cbk,
    float* __restrict__ out)
{
    extern __shared__ char smc[];
    float* res     = (float*)(smc + SM_RES);
    float* rr_s    = (float*)(smc + SM_RRS);
    int*   cand    = (int*)(smc + SM_CAND);
    int*   bestIdx = (int*)(smc + SM_BIDX);
    const uint32_t sb_ebuf = smem_u32(smc + SM_EBUF);

    const int tid  = threadIdx.x;
    const int warp = tid >> 5, lane = tid & 31;
    const int row0 = blockIdx.x * VROWS;
    const int rg   = warp >> 1;                 // rowgroup (16 rows)
    const int chf  = warp & 1;                  // code half within tile
    const int tig  = lane & 3, gid = lane >> 2;
    const int r_lo = rg * 16 + gid, r_hi = r_lo + 8;
    const int codeL = chf * 32 + (lane & 7);    // smem code row this lane reads
    const int grnb  = lane >> 3;                // 0..3 (x4 block id)

    // residual := ze
    #pragma unroll
    for (int i = 0; i < 8; i++) {
        int g = tid + i * 256;
        int r = g >> 5, dq = g & 31;
        *(float4*)(res + r * RES_STRIDE + dq * 4) =
            *(const float4*)(ze + (size_t)(row0 + r) * DIM + dq * 4);
    }
    __syncthreads();

    for (int m = 0; m < MBOOK; m++) {
        const float* Eb = cbk + (size_t)m * KCODES * DIM;
        const float* nb = g_nn + m * KCODES;
        const __nv_bfloat16* bh = g_cbh + (size_t)m * KCODES * DIM;
        const __nv_bfloat16* bm = g_cbm + (size_t)m * KCODES * DIM;

        // kick off tile 0 staging (async; overlaps everything below)
        stageE(sb_ebuf, bh, bm, 0, tid);

        // emit res_s[m]
        {
            size_t ob = RES_OFF + (size_t)m * NROWS * DIM + (size_t)row0 * DIM;
            #pragma unroll
            for (int i = 0; i < 8; i++) {
                int g = tid + i * 256;
                int r = g >> 5, dq = g & 31;
                *(float4*)(out + ob + (size_t)r * DIM + dq * 4) =
                    *(const float4*)(res + r * RES_STRIDE + dq * 4);
            }
        }

        // per-row ||r||^2 (sequential dim order)
        if (tid < VROWS) {
            float s = 0.f;
            #pragma unroll
            for (int dq = 0; dq < 32; dq++) {
                float4 v = *(const float4*)(res + tid * RES_STRIDE + dq * 4);
                s = fmaf(v.x, v.x, s); s = fmaf(v.y, v.y, s);
                s = fmaf(v.z, v.z, s); s = fmaf(v.w, v.w, s);
            }
            rr_s[tid] = s;
        }
        __syncthreads();

        const float rr_lo = rr_s[r_lo], rr_hi = rr_s[r_hi];

        // build A fragments (2 limbs) in registers from res smem
        uint32_t Ah[8][4], Am[8][4];
        #pragma unroll
        for (int ks = 0; ks < 8; ks++) {
            int c0 = ks * 16 + 2 * tig;
            split2(*(const float2*)(res + r_lo * RES_STRIDE + c0),     Ah[ks][0], Am[ks][0]);
            split2(*(const float2*)(res + r_hi * RES_STRIDE + c0),     Ah[ks][1], Am[ks][1]);
            split2(*(const float2*)(res + r_lo * RES_STRIDE + c0 + 8), Ah[ks][2], Am[ks][2]);
            split2(*(const float2*)(res + r_hi * RES_STRIDE + c0 + 8), Ah[ks][3], Am[ks][3]);
        }

        // top-2 approx candidates per thread for each of its 2 rows
        float b1_lo = FLT_MAX, b2_lo = FLT_MAX, b1_hi = FLT_MAX, b2_hi = FLT_MAX;
        int   i1_lo = 0x7fffffff, i2_lo = 0x7fffffff;
        int   i1_hi = 0x7fffffff, i2_hi = 0x7fffffff;

        for (int t = 0; t < NT; t++) {
            if (t + 1 < NT) {
                stageE(sb_ebuf + ((t + 1) & 1) * EBUF_B, bh, bm, t + 1, tid);
                asm volatile("cp.async.wait_group 1;");
            } else {
                asm volatile("cp.async.wait_group 0;");
            }
            __syncthreads();

            const uint32_t ebuf = sb_ebuf + (t & 1) * EBUF_B;
            const int tbase = t * TC + chf * 32;

            #pragma unroll
            for (int ng = 0; ng < 4; ng++) {
                const uint32_t rowa = ebuf + (codeL + ng * 8) * 256;
                const int cs = codeL & 7;
                float d0 = 0.f, d1 = 0.f, d2 = 0.f, d3 = 0.f;

                #pragma unroll
                for (int kp = 0; kp < 4; kp++) {
                    uint32_t goff = (uint32_t)(((kp * 4 + grnb) ^ cs) << 4);
                    uint32_t h0, h1, h2, h3, m0, m1, m2, m3;
                    LDSM4(h0, h1, h2, h3, rowa + goff);
                    LDSM4(m0, m1, m2, m3, rowa + (TC * 256) + goff);
                    const int ke = kp * 2, ko = ke + 1;
                    MMA16816(d0,d1,d2,d3, Ah[ke][0],Ah[ke][1],Ah[ke][2],Ah[ke][3], h0,h1);
                    MMA16816(d0,d1,d2,d3, Ah[ke][0],Ah[ke][1],Ah[ke][2],Ah[ke][3], m0,m1);
                    MMA16816(d0,d1,d2,d3, Am[ke][0],Am[ke][1],Am[ke][2],Am[ke][3], h0,h1);
                    MMA16816(d0,d1,d2,d3, Ah[ko][0],Ah[ko][1],Ah[ko][2],Ah[ko][3], h2,h3);
                    MMA16816(d0,d1,d2,d3, Ah[ko][0],Ah[ko][1],Ah[ko][2],Ah[ko][3], m2,m3);
                    MMA16816(d0,d1,d2,d3, Am[ko][0],Am[ko][1],Am[ko][2],Am[ko][3], h2,h3);
                }

                // approx scores for codes (cA, cA+1) x rows (r_lo, r_hi)
                const int cA = tbase + ng * 8 + 2 * tig;
                const float eeA = __ldg(nb + cA), eeB = __ldg(nb + cA + 1);
                float s;
                s = fmaf(-2.0f, d0, rr_lo) + eeA;
                if (s < b1_lo) { b2_lo = b1_lo; i2_lo = i1_lo; b1_lo = s; i1_lo = cA; }
                else if (s < b2_lo) { b2_lo = s; i2_lo = cA; }
                s = fmaf(-2.0f, d1, rr_lo) + eeB;
                if (s < b1_lo) { b2_lo = b1_lo; i2_lo = i1_lo; b1_lo = s; i1_lo = cA + 1; }
                else if (s < b2_lo) { b2_lo = s; i2_lo = cA + 1; }
                s = fmaf(-2.0f, d2, rr_hi) + eeA;
                if (s < b1_hi) { b2_hi = b1_hi; i2_hi = i1_hi; b1_hi = s; i1_hi = cA; }
                else if (s < b2_hi) { b2_hi = s; i2_hi = cA; }
                s = fmaf(-2.0f, d3, rr_hi) + eeB;
                if (s < b1_hi) { b2_hi = b1_hi; i2_hi = i1_hi; b1_hi = s; i1_hi = cA + 1; }
                else if (s < b2_hi) { b2_hi = s; i2_hi = cA + 1; }
            }
            __syncthreads();
        }

        // deposit candidates: 8 threads/row x 2 = 16 slots/row
        {
            int slot = chf * 8 + tig * 2;
            cand[r_lo * 16 + slot]     = i1_lo;
            cand[r_lo * 16 + slot + 1] = i2_lo;
            cand[r_hi * 16 + slot]     = i1_hi;
            cand[r_hi * 16 + slot + 1] = i2_hi;
        }
        __syncthreads();

        // exact fp32 rescore of the 16 candidates per row (reference rounding)
        #pragma unroll 1
        for (int rw = 0; rw < VROWS / 8; rw++) {
            int row = warp * 8 + rw;
            int c = cand[row * 16 + (lane & 15)];
            const float* e  = Eb + (size_t)c * DIM + (lane >> 4) * 64;
            const float* rp = res + row * RES_STRIDE + (lane >> 4) * 64;
            float p = 0.f;
            #pragma unroll
            for (int d2 = 0; d2 < 64; d2++)
                p = fmaf(rp[d2], __ldg(e + d2), p);
            float q = __shfl_xor_sync(0xffffffffu, p, 16);
            float lo = (lane < 16) ? p : q, hi = (lane < 16) ? q : p;
            float dot = lo + hi;
            float dd = fmaf(-2.0f, dot, rr_s[row]) + __ldg(nb + c);
            float bv = dd; int bi = c;
            #pragma unroll
            for (int off = 8; off >= 1; off >>= 1) {
                float ov = __shfl_down_sync(0xffffffffu, bv, off);
                int   oi = __shfl_down_sync(0xffffffffu, bi, off);
                if (ov < bv || (ov == bv && oi < bi)) { bv = ov; bi = oi; }
            }
            if (lane == 0) bestIdx[row] = bi;
        }
        __syncthreads();

        // quantize: emit ce_s[m], residual -= ce (fp32 codebook, exact)
        #pragma unroll 1
        for (int rw = 0; rw < VROWS / 8; rw++) {
            int row = warp * 8 + rw;
            int idx = bestIdx[row];
            float4 cv = __ldg((const float4*)(Eb + (size_t)idx * DIM) + lane);
            size_t ob = CE_OFF + (size_t)m * NROWS * DIM
                      + (size_t)(row0 + row) * DIM;
            *(float4*)(out + ob + lane * 4) = cv;
            float4* rp = (float4*)(res + row * RES_STRIDE + lane * 4);
            float4 rv = *rp;
            rv.x -= cv.x; rv.y -= cv.y; rv.z -= cv.z; rv.w -= cv.w;
            *rp = rv;
        }
        __syncthreads();
    }
}

// ---------------------------------------------------------------------------
// di = ze + (sum_m ce_s[m] - ze)
// ---------------------------------------------------------------------------
__global__ void di_kernel(const float* __restrict__ out)
{
    int i = blockIdx.x * 256 + threadIdx.x;
    float zev = g_ze[i];
    float zq = 0.f;
    #pragma unroll
    for (int m = 0; m < MBOOK; m++)
        zq += out[CE_OFF + (size_t)m * NROWS * DIM + i];
    g_di[i] = zev + (zq - zev);
}

// ---------------------------------------------------------------------------
extern "C" void kernel_launch(void* const* d_in, const int* in_sizes, int n_in,
                              void* d_out, int out_size)
{
    const float* x   = (const float*)d_in[0];
    const float* W1  = (const float*)d_in[1];
    const float* b1  = (const float*)d_in[2];
    const float* g1  = (const float*)d_in[3];
    const float* be1 = (const float*)d_in[4];
    const float* rm1 = (const float*)d_in[5];
    const float* rv1 = (const float*)d_in[6];
    const float* W2  = (const float*)d_in[7];
    const float* b2  = (const float*)d_in[8];
    const float* g2  = (const float*)d_in[9];
    const float* be2 = (const float*)d_in[10];
    const float* rm2 = (const float*)d_in[11];
    const float* rv2 = (const float*)d_in[12];
    const float* W3  = (const float*)d_in[13];
    const float* b3  = (const float*)d_in[14];
    const float* cbk = (const float*)d_in[15];
    const float* W4  = (const float*)d_in[16];
    const float* b4  = (const float*)d_in[17];
    const float* g3  = (const float*)d_in[18];
    const float* be3 = (const float*)d_in[19];
    const float* rm3 = (const float*)d_in[20];
    const float* rv3 = (const float*)d_in[21];
    const float* W5  = (const float*)d_in[22];
    const float* b5  = (const float*)d_in[23];
    const float* g4  = (const float*)d_in[24];
    const float* be4 = (const float*)d_in[25];
    const float* rm4 = (const float*)d_in[26];
    const float* rv4 = (const float*)d_in[27];
    const float* W6  = (const float*)d_in[28];
    const float* b6  = (const float*)d_in[29];
    float* out = (float*)d_out;

    float *h1, *h2, *ze, *di, *t1, *t2;
    cudaGetSymbolAddress((void**)&h1, g_h1);
    cudaGetSymbolAddress((void**)&h2, g_h2);
    cudaGetSymbolAddress((void**)&ze, g_ze);
    cudaGetSymbolAddress((void**)&di, g_di);
    cudaGetSymbolAddress((void**)&t1, g_t1);
    cudaGetSymbolAddress((void**)&t2, g_t2);

    cudaFuncSetAttribute(vq_kernel,
                         cudaFuncAttributeMaxDynamicSharedMemorySize, SM_TOTAL);

    // codebook prep (launches 0,1)
    norm_kernel<<<MBOOK * KCODES / 256, 256>>>(cbk);
    split_kernel<<<MBOOK * KCODES * DIM / 256, 256>>>(cbk);

    // encoder (launches 2,3,4)
    gemm_kernel<256, 128, true,  true ><<<dim3(2, 128), 256>>>(x,  W1, b1, g1, be1, rm1, rv1, h1);
    gemm_kernel<128, 256, true,  true ><<<dim3(4, 128), 256>>>(h1, W2, b2, g2, be2, rm2, rv2, h2);
    gemm_kernel<256, 128, false, false><<<dim3(2, 128), 256>>>(h2, W3, b3, nullptr, nullptr, nullptr, nullptr, ze);

    // residual VQ (launch 5 -> ncu -s 5 captures this)
    vq_kernel<<<NROWS / VROWS, 256, SM_TOTAL>>>(ze, cbk, out);

    // straight-through: di = ze + (zq - ze)
    di_kernel<<<NROWS * DIM / 256, 256>>>(out);

    // decoder
    gemm_kernel<128, 256, true,  true ><<<dim3(4, 128), 256>>>(di, W4, b4, g3, be3, rm3, rv3, t1);
    gemm_kernel<256, 128, true,  true ><<<dim3(2, 128), 256>>>(t1, W5, b5, g4, be4, rm4, rv4, t2);
    gemm_kernel<128, 256, false, false><<<dim3(4, 128), 256>>>(t2, W6, b6, nullptr, nullptr, nullptr, nullptr, out);
}

// round 8
// speedup vs baseline: 2.6462x; 1.0837x over previous
#include <cuda_runtime.h>
#include <cuda_bf16.h>
#include <math.h>
#include <float.h>
#include <stdint.h>

#define NROWS   8192
#define IN_DIM  256
#define DIM     128
#define KCODES  8192
#define MBOOK   8
#define EPSBN   1e-5f

// output layout: x_hat [8192,256] ++ res_s [8,8192,128] ++ ce_s [8,8192,128]
#define RES_OFF ((size_t)NROWS * IN_DIM)
#define CE_OFF  (RES_OFF + (size_t)MBOOK * NROWS * DIM)

// scratch (static device allocations only)
__device__ float g_h1[NROWS * 128];
__device__ float g_h2[NROWS * 256];
__device__ float g_ze[NROWS * DIM];
__device__ float g_di[NROWS * DIM];
__device__ float g_t1[NROWS * 256];
__device__ float g_t2[NROWS * 128];
__device__ float g_nn[MBOOK * KCODES];                 // ||e||^2 fp32
__device__ __nv_bfloat16 g_cbh[MBOOK * KCODES * DIM];  // bf16 hi limb of E

// ---------------------------------------------------------------------------
// mma.sync / ldmatrix helpers (baseline PTX, compiles for compute_103)
// ---------------------------------------------------------------------------
#define MMA16816(d0,d1,d2,d3,a0,a1,a2,a3,b0,b1) \
    asm volatile("mma.sync.aligned.m16n8k16.row.col.f32.bf16.bf16.f32 " \
        "{%0,%1,%2,%3}, {%4,%5,%6,%7}, {%8,%9}, {%0,%1,%2,%3};" \
        : "+f"(d0), "+f"(d1), "+f"(d2), "+f"(d3) \
        : "r"(a0), "r"(a1), "r"(a2), "r"(a3), "r"(b0), "r"(b1))

#define LDSM4(r0,r1,r2,r3,addr) \
    asm volatile("ldmatrix.sync.aligned.m8n8.x4.shared.b16 {%0,%1,%2,%3}, [%4];" \
        : "=r"(r0), "=r"(r1), "=r"(r2), "=r"(r3) : "r"(addr))

__device__ __forceinline__ uint32_t smem_u32(const void* p) {
    uint32_t a;
    asm("{ .reg .u64 t; cvta.to.shared.u64 t, %1; cvt.u32.u64 %0, t; }"
        : "=r"(a) : "l"(p));
    return a;
}

__device__ __forceinline__ uint32_t pack_bf16(__nv_bfloat16 a, __nv_bfloat16 b) {
    return (uint32_t)__bfloat16_as_ushort(a)
         | ((uint32_t)__bfloat16_as_ushort(b) << 16);
}

// split float2 into 2 bf16x2 limbs
__device__ __forceinline__ void split2(float2 v, uint32_t& h, uint32_t& m) {
    __nv_bfloat16 h0 = __float2bfloat16(v.x); float hf0 = __bfloat162float(h0);
    __nv_bfloat16 m0 = __float2bfloat16(v.x - hf0);
    __nv_bfloat16 h1 = __float2bfloat16(v.y); float hf1 = __bfloat162float(h1);
    __nv_bfloat16 m1 = __float2bfloat16(v.y - hf1);
    h = pack_bf16(h0, h1); m = pack_bf16(m0, m1);
}

// top-4 running-min insert (rarely-taken branch)
__device__ __forceinline__ void top4(float s, int c,
    float& b1, float& b2, float& b3, float& b4,
    int& i1, int& i2, int& i3, int& i4)
{
    if (s < b4) {
        if (s < b2) {
            b4 = b3; i4 = i3; b3 = b2; i3 = i2;
            if (s < b1) { b2 = b1; i2 = i1; b1 = s; i1 = c; }
            else        { b2 = s;  i2 = c; }
        } else {
            if (s < b3) { b4 = b3; i4 = i3; b3 = s; i3 = c; }
            else        { b4 = s;  i4 = c; }
        }
    }
}

// ---------------------------------------------------------------------------
// Generic tiled GEMM: C = act(bn(A[N,KD] @ W[KD,P] + bias))
// ---------------------------------------------------------------------------
template<int KD, int P, bool BN, bool RELU>
__global__ void __launch_bounds__(256) gemm_kernel(
    const float* __restrict__ A, const float* __restrict__ W,
    const float* __restrict__ bias,
    const float* __restrict__ gg, const float* __restrict__ be,
    const float* __restrict__ rm, const float* __restrict__ rv,
    float* __restrict__ C)
{
    __shared__ __align__(16) float As[16][68];
    __shared__ __align__(16) float Ws[16][68];
    const int tid = threadIdx.x;
    const int rid = tid >> 4, cid = tid & 15;
    const int row0 = blockIdx.y * 64, col0 = blockIdx.x * 64;
    float acc[4][4] = {};

    for (int k0 = 0; k0 < KD; k0 += 16) {
        __syncthreads();
        #pragma unroll
        for (int i = 0; i < 4; i++) {
            int idx = tid + i * 256;
            int r  = idx >> 4, kk  = idx & 15;
            As[kk][r] = A[(size_t)(row0 + r) * KD + (k0 + kk)];
            int kk2 = idx >> 6, c  = idx & 63;
            Ws[kk2][c] = W[(size_t)(k0 + kk2) * P + (col0 + c)];
        }
        __syncthreads();
        #pragma unroll
        for (int kk = 0; kk < 16; kk++) {
            float4 a = *(const float4*)&As[kk][rid * 4];
            float4 w = *(const float4*)&Ws[kk][cid * 4];
            float av[4] = {a.x, a.y, a.z, a.w};
            float wv[4] = {w.x, w.y, w.z, w.w};
            #pragma unroll
            for (int r = 0; r < 4; r++)
                #pragma unroll
                for (int c = 0; c < 4; c++)
                    acc[r][c] += av[r] * wv[c];
        }
    }
    #pragma unroll
    for (int r = 0; r < 4; r++) {
        int row = row0 + rid * 4 + r;
        #pragma unroll
        for (int c = 0; c < 4; c++) {
            int col = col0 + cid * 4 + c;
            float v = acc[r][c] + bias[col];
            if constexpr (BN)
                v = (v - rm[col]) / sqrtf(rv[col] + EPSBN) * gg[col] + be[col];
            if constexpr (RELU)
                v = fmaxf(v, 0.0f);
            C[(size_t)row * P + col] = v;
        }
    }
}

// ---------------------------------------------------------------------------
// codebook prep: ||e||^2 fp32 + bf16 hi-limb
// ---------------------------------------------------------------------------
__global__ void norm_kernel(const float* __restrict__ cbk)
{
    int i = blockIdx.x * 256 + threadIdx.x;
    const float4* p = (const float4*)(cbk + (size_t)i * DIM);
    float s = 0.f;
    #pragma unroll
    for (int j = 0; j < DIM / 4; j++) {
        float4 q = p[j];
        s += q.x * q.x + q.y * q.y + q.z * q.z + q.w * q.w;
    }
    g_nn[i] = s;
}

__global__ void split_kernel(const float* __restrict__ cbk)
{
    size_t i = (size_t)blockIdx.x * 256 + threadIdx.x;
    g_cbh[i] = __float2bfloat16(cbk[i]);
}

// ---------------------------------------------------------------------------
// Residual VQ v8: 2-term mma.sync scoring ((r_h + r_m) . e_h)
//                 + per-thread top-4 capture + exact fp32 rescore (32 cands).
//  CTA: 64 rows, 8 warps. warp = rowgroup(16 rows) x code-half(64 of 128-tile).
//  Only the hi limb of E is staged (e_m never needed for these terms).
//  Rescore reproduces reference rounding: d = (rr - 2*dot_fp32) + ee.
// ---------------------------------------------------------------------------
#define VROWS 64
#define TC    128
#define NT    (KCODES / TC)
#define RES_STRIDE 132
#define EBUF_B (TC * 256)                  // 32768 bytes per buffer

// smem byte offsets
#define SM_RES  0                          // 64*132*4 = 33792
#define SM_RRS  33792                      // 64 floats
#define SM_CAND 34048                      // 64*32 ints = 8192
#define SM_BIDX 42240                      // 64 ints
#define SM_EBUF 42496                      // 2 * EBUF_B
#define SM_TOTAL (SM_EBUF + 2 * EBUF_B)    // 108032

__device__ __forceinline__ void stageE(uint32_t ebuf_sm,
                                       const __nv_bfloat16* __restrict__ bh,
                                       int tile, int tid)
{
    #pragma unroll
    for (int i = 0; i < 8; i++) {
        int ch = tid + i * 256;                   // 0..2047
        int code = ch >> 4, g = ch & 15;
        const __nv_bfloat16* src = bh + ((size_t)(tile * TC + code) << 7) + (g << 3);
        uint32_t dst = ebuf_sm + code * 256 + ((g ^ (code & 7)) << 4);
        asm volatile("cp.async.cg.shared.global [%0], [%1], 16;"
                     :: "r"(dst), "l"(src));
    }
    asm volatile("cp.async.commit_group;");
}

__global__ void __launch_bounds__(256, 1) vq_kernel(
    const float* __restrict__ ze, const float* __restrict__ cbk,
    float* __restrict__ out)
{
    extern __shared__ char smc[];
    float* res     = (float*)(smc + SM_RES);
    float* rr_s    = (float*)(smc + SM_RRS);
    int*   cand    = (int*)(smc + SM_CAND);
    int*   bestIdx = (int*)(smc + SM_BIDX);
    const uint32_t sb_ebuf = smem_u32(smc + SM_EBUF);

    const int tid  = threadIdx.x;
    const int warp = tid >> 5, lane = tid & 31;
    const int row0 = blockIdx.x * VROWS;
    const int rg   = warp >> 1;                 // rowgroup (16 rows)
    const int chf  = warp & 1;                  // code half within tile (64)
    const int tig  = lane & 3, gid = lane >> 2;
    const int r_lo = rg * 16 + gid, r_hi = r_lo + 8;
    const int codeL = chf * 64 + (lane & 7);    // smem code row base this lane reads
    const int grnb  = lane >> 3;                // 0..3 (x4 block id)
    const int cs    = lane & 7;                 // swizzle key (codeL & 7)

    // residual := ze
    #pragma unroll
    for (int i = 0; i < 8; i++) {
        int g = tid + i * 256;
        int r = g >> 5, dq = g & 31;
        *(float4*)(res + r * RES_STRIDE + dq * 4) =
            *(const float4*)(ze + (size_t)(row0 + r) * DIM + dq * 4);
    }
    __syncthreads();

    for (int m = 0; m < MBOOK; m++) {
        const float* Eb = cbk + (size_t)m * KCODES * DIM;
        const float* nb = g_nn + m * KCODES;
        const __nv_bfloat16* bh = g_cbh + (size_t)m * KCODES * DIM;

        // kick off tile 0 staging (async; overlaps everything below)
        stageE(sb_ebuf, bh, 0, tid);

        // emit res_s[m]
        {
            size_t ob = RES_OFF + (size_t)m * NROWS * DIM + (size_t)row0 * DIM;
            #pragma unroll
            for (int i = 0; i < 8; i++) {
                int g = tid + i * 256;
                int r = g >> 5, dq = g & 31;
                *(float4*)(out + ob + (size_t)r * DIM + dq * 4) =
                    *(const float4*)(res + r * RES_STRIDE + dq * 4);
            }
        }

        // per-row ||r||^2 (sequential dim order)
        if (tid < VROWS) {
            float s = 0.f;
            #pragma unroll
            for (int dq = 0; dq < 32; dq++) {
                float4 v = *(const float4*)(res + tid * RES_STRIDE + dq * 4);
                s = fmaf(v.x, v.x, s); s = fmaf(v.y, v.y, s);
                s = fmaf(v.z, v.z, s); s = fmaf(v.w, v.w, s);
            }
            rr_s[tid] = s;
        }
        __syncthreads();

        const float rr_lo = rr_s[r_lo], rr_hi = rr_s[r_hi];

        // build A fragments (2 limbs) in registers from res smem
        uint32_t Ah[8][4], Am[8][4];
        #pragma unroll
        for (int ks = 0; ks < 8; ks++) {
            int c0 = ks * 16 + 2 * tig;
            split2(*(const float2*)(res + r_lo * RES_STRIDE + c0),     Ah[ks][0], Am[ks][0]);
            split2(*(const float2*)(res + r_hi * RES_STRIDE + c0),     Ah[ks][1], Am[ks][1]);
            split2(*(const float2*)(res + r_lo * RES_STRIDE + c0 + 8), Ah[ks][2], Am[ks][2]);
            split2(*(const float2*)(res + r_hi * RES_STRIDE + c0 + 8), Ah[ks][3], Am[ks][3]);
        }

        // top-4 approx candidates per thread for each of its 2 rows
        float b1l = FLT_MAX, b2l = FLT_MAX, b3l = FLT_MAX, b4l = FLT_MAX;
        float b1h = FLT_MAX, b2h = FLT_MAX, b3h = FLT_MAX, b4h = FLT_MAX;
        int   i1l = 0x7fffffff, i2l = 0x7fffffff, i3l = 0x7fffffff, i4l = 0x7fffffff;
        int   i1h = 0x7fffffff, i2h = 0x7fffffff, i3h = 0x7fffffff, i4h = 0x7fffffff;

        for (int t = 0; t < NT; t++) {
            if (t + 1 < NT) {
                stageE(sb_ebuf + ((t + 1) & 1) * EBUF_B, bh, t + 1, tid);
                asm volatile("cp.async.wait_group 1;");
            } else {
                asm volatile("cp.async.wait_group 0;");
            }
            __syncthreads();

            const uint32_t ebuf = sb_ebuf + (t & 1) * EBUF_B;
            const int tbase = t * TC + chf * 64;

            #pragma unroll
            for (int ng = 0; ng < 8; ng++) {
                const uint32_t rowa = ebuf + (codeL + ng * 8) * 256;
                float d0 = 0.f, d1 = 0.f, d2 = 0.f, d3 = 0.f;

                #pragma unroll
                for (int kp = 0; kp < 4; kp++) {
                    uint32_t goff = (uint32_t)(((kp * 4 + grnb) ^ cs) << 4);
                    uint32_t h0, h1, h2, h3;
                    LDSM4(h0, h1, h2, h3, rowa + goff);
                    const int ke = kp * 2, ko = ke + 1;
                    MMA16816(d0,d1,d2,d3, Ah[ke][0],Ah[ke][1],Ah[ke][2],Ah[ke][3], h0,h1);
                    MMA16816(d0,d1,d2,d3, Am[ke][0],Am[ke][1],Am[ke][2],Am[ke][3], h0,h1);
                    MMA16816(d0,d1,d2,d3, Ah[ko][0],Ah[ko][1],Ah[ko][2],Ah[ko][3], h2,h3);
                    MMA16816(d0,d1,d2,d3, Am[ko][0],Am[ko][1],Am[ko][2],Am[ko][3], h2,h3);
                }

                // approx scores for codes (cA, cA+1) x rows (r_lo, r_hi)
                const int cA = tbase + ng * 8 + 2 * tig;
                const float eeA = __ldg(nb + cA), eeB = __ldg(nb + cA + 1);
                top4(fmaf(-2.0f, d0, rr_lo) + eeA, cA,     b1l,b2l,b3l,b4l, i1l,i2l,i3l,i4l);
                top4(fmaf(-2.0f, d1, rr_lo) + eeB, cA + 1, b1l,b2l,b3l,b4l, i1l,i2l,i3l,i4l);
                top4(fmaf(-2.0f, d2, rr_hi) + eeA, cA,     b1h,b2h,b3h,b4h, i1h,i2h,i3h,i4h);
                top4(fmaf(-2.0f, d3, rr_hi) + eeB, cA + 1, b1h,b2h,b3h,b4h, i1h,i2h,i3h,i4h);
            }
            __syncthreads();
        }

        // deposit candidates: 8 threads/row x 4 = 32 slots/row
        {
            int slot = (chf * 4 + tig) * 4;
            cand[r_lo * 32 + slot]     = i1l;
            cand[r_lo * 32 + slot + 1] = i2l;
            cand[r_lo * 32 + slot + 2] = i3l;
            cand[r_lo * 32 + slot + 3] = i4l;
            cand[r_hi * 32 + slot]     = i1h;
            cand[r_hi * 32 + slot + 1] = i2h;
            cand[r_hi * 32 + slot + 2] = i3h;
            cand[r_hi * 32 + slot + 3] = i4h;
        }
        __syncthreads();

        // exact fp32 rescore of the 32 candidates per row (reference rounding)
        #pragma unroll 1
        for (int rw = 0; rw < VROWS / 8; rw++) {
            int row = warp * 8 + rw;
            int c = cand[row * 32 + lane];
            const float4* e  = (const float4*)(Eb + (size_t)c * DIM);
            const float4* rp = (const float4*)(res + row * RES_STRIDE);
            float p = 0.f;
            #pragma unroll
            for (int i = 0; i < 32; i++) {
                float4 rv = rp[i];
                float4 ev = __ldg(e + i);
                p = fmaf(rv.x, ev.x, p); p = fmaf(rv.y, ev.y, p);
                p = fmaf(rv.z, ev.z, p); p = fmaf(rv.w, ev.w, p);
            }
            float dd = fmaf(-2.0f, p, rr_s[row]) + __ldg(nb + c);
            float bv = dd; int bi = c;
            #pragma unroll
            for (int off = 16; off >= 1; off >>= 1) {
                float ov = __shfl_down_sync(0xffffffffu, bv, off);
                int   oi = __shfl_down_sync(0xffffffffu, bi, off);
                if (ov < bv || (ov == bv && oi < bi)) { bv = ov; bi = oi; }
            }
            if (lane == 0) bestIdx[row] = bi;
        }
        __syncthreads();

        // quantize: emit ce_s[m], residual -= ce (fp32 codebook, exact)
        #pragma unroll 1
        for (int rw = 0; rw < VROWS / 8; rw++) {
            int row = warp * 8 + rw;
            int idx = bestIdx[row];
            float4 cv = __ldg((const float4*)(Eb + (size_t)idx * DIM) + lane);
            size_t ob = CE_OFF + (size_t)m * NROWS * DIM
                      + (size_t)(row0 + row) * DIM;
            *(float4*)(out + ob + lane * 4) = cv;
            float4* rp = (float4*)(res + row * RES_STRIDE + lane * 4);
            float4 rv = *rp;
            rv.x -= cv.x; rv.y -= cv.y; rv.z -= cv.z; rv.w -= cv.w;
            *rp = rv;
        }
        __syncthreads();
    }
}

// ---------------------------------------------------------------------------
// di = ze + (sum_m ce_s[m] - ze)
// ---------------------------------------------------------------------------
__global__ void di_kernel(const float* __restrict__ out)
{
    int i = blockIdx.x * 256 + threadIdx.x;
    float zev = g_ze[i];
    float zq = 0.f;
    #pragma unroll
    for (int m = 0; m < MBOOK; m++)
        zq += out[CE_OFF + (size_t)m * NROWS * DIM + i];
    g_di[i] = zev + (zq - zev);
}

// ---------------------------------------------------------------------------
extern "C" void kernel_launch(void* const* d_in, const int* in_sizes, int n_in,
                              void* d_out, int out_size)
{
    const float* x   = (const float*)d_in[0];
    const float* W1  = (const float*)d_in[1];
    const float* b1  = (const float*)d_in[2];
    const float* g1  = (const float*)d_in[3];
    const float* be1 = (const float*)d_in[4];
    const float* rm1 = (const float*)d_in[5];
    const float* rv1 = (const float*)d_in[6];
    const float* W2  = (const float*)d_in[7];
    const float* b2  = (const float*)d_in[8];
    const float* g2  = (const float*)d_in[9];
    const float* be2 = (const float*)d_in[10];
    const float* rm2 = (const float*)d_in[11];
    const float* rv2 = (const float*)d_in[12];
    const float* W3  = (const float*)d_in[13];
    const float* b3  = (const float*)d_in[14];
    const float* cbk = (const float*)d_in[15];
    const float* W4  = (const float*)d_in[16];
    const float* b4  = (const float*)d_in[17];
    const float* g3  = (const float*)d_in[18];
    const float* be3 = (const float*)d_in[19];
    const float* rm3 = (const float*)d_in[20];
    const float* rv3 = (const float*)d_in[21];
    const float* W5  = (const float*)d_in[22];
    const float* b5  = (const float*)d_in[23];
    const float* g4  = (const float*)d_in[24];
    const float* be4 = (const float*)d_in[25];
    const float* rm4 = (const float*)d_in[26];
    const float* rv4 = (const float*)d_in[27];
    const float* W6  = (const float*)d_in[28];
    const float* b6  = (const float*)d_in[29];
    float* out = (float*)d_out;

    float *h1, *h2, *ze, *di, *t1, *t2;
    cudaGetSymbolAddress((void**)&h1, g_h1);
    cudaGetSymbolAddress((void**)&h2, g_h2);
    cudaGetSymbolAddress((void**)&ze, g_ze);
    cudaGetSymbolAddress((void**)&di, g_di);
    cudaGetSymbolAddress((void**)&t1, g_t1);
    cudaGetSymbolAddress((void**)&t2, g_t2);

    cudaFuncSetAttribute(vq_kernel,
                         cudaFuncAttributeMaxDynamicSharedMemorySize, SM_TOTAL);

    // codebook prep (launches 0,1)
    norm_kernel<<<MBOOK * KCODES / 256, 256>>>(cbk);
    split_kernel<<<MBOOK * KCODES * DIM / 256, 256>>>(cbk);

    // encoder (launches 2,3,4)
    gemm_kernel<256, 128, true,  true ><<<dim3(2, 128), 256>>>(x,  W1, b1, g1, be1, rm1, rv1, h1);
    gemm_kernel<128, 256, true,  true ><<<dim3(4, 128), 256>>>(h1, W2, b2, g2, be2, rm2, rv2, h2);
    gemm_kernel<256, 128, false, false><<<dim3(2, 128), 256>>>(h2, W3, b3, nullptr, nullptr, nullptr, nullptr, ze);

    // residual VQ (launch 5 -> ncu -s 5 captures this)
    vq_kernel<<<NROWS / VROWS, 256, SM_TOTAL>>>(ze, cbk, out);

    // straight-through: di = ze + (zq - ze)
    di_kernel<<<NROWS * DIM / 256, 256>>>(out);

    // decoder
    gemm_kernel<128, 256, true,  true ><<<dim3(4, 128), 256>>>(di, W4, b4, g3, be3, rm3, rv3, t1);
    gemm_kernel<256, 128, true,  true ><<<dim3(2, 128), 256>>>(t1, W5, b5, g4, be4, rm4, rv4, t2);
    gemm_kernel<128, 256, false, false><<<dim3(4, 128), 256>>>(t2, W6, b6, nullptr, nullptr, nullptr, nullptr, out);
}

// round 9
// speedup vs baseline: 3.5227x; 1.3312x over previous
#include <cuda_runtime.h>
#include <cuda_bf16.h>
#include <math.h>
#include <float.h>
#include <stdint.h>

#define NROWS   8192
#define IN_DIM  256
#define DIM     128
#define KCODES  8192
#define MBOOK   8
#define EPSBN   1e-5f

// output layout: x_hat [8192,256] ++ res_s [8,8192,128] ++ ce_s [8,8192,128]
#define RES_OFF ((size_t)NROWS * IN_DIM)
#define CE_OFF  (RES_OFF + (size_t)MBOOK * NROWS * DIM)

// scratch (static device allocations only)
__device__ float g_h1[NROWS * 128];
__device__ float g_h2[NROWS * 256];
__device__ float g_ze[NROWS * DIM];
__device__ float g_di[NROWS * DIM];
__device__ float g_t1[NROWS * 256];
__device__ float g_t2[NROWS * 128];
__device__ float g_nn[MBOOK * KCODES];                 // ||e||^2 fp32
__device__ __nv_bfloat16 g_cbh[MBOOK * KCODES * DIM];  // bf16 hi limb of E

// ---------------------------------------------------------------------------
// mma.sync / ldmatrix helpers (baseline PTX, compiles for compute_103)
// ---------------------------------------------------------------------------
#define MMA16816(d0,d1,d2,d3,a0,a1,a2,a3,b0,b1) \
    asm volatile("mma.sync.aligned.m16n8k16.row.col.f32.bf16.bf16.f32 " \
        "{%0,%1,%2,%3}, {%4,%5,%6,%7}, {%8,%9}, {%0,%1,%2,%3};" \
        : "+f"(d0), "+f"(d1), "+f"(d2), "+f"(d3) \
        : "r"(a0), "r"(a1), "r"(a2), "r"(a3), "r"(b0), "r"(b1))

#define LDSM4(r0,r1,r2,r3,addr) \
    asm volatile("ldmatrix.sync.aligned.m8n8.x4.shared.b16 {%0,%1,%2,%3}, [%4];" \
        : "=r"(r0), "=r"(r1), "=r"(r2), "=r"(r3) : "r"(addr))

__device__ __forceinline__ uint32_t smem_u32(const void* p) {
    uint32_t a;
    asm("{ .reg .u64 t; cvta.to.shared.u64 t, %1; cvt.u32.u64 %0, t; }"
        : "=r"(a) : "l"(p));
    return a;
}

__device__ __forceinline__ uint32_t pack_bf16f(float a, float b) {
    return (uint32_t)__bfloat16_as_ushort(__float2bfloat16(a))
         | ((uint32_t)__bfloat16_as_ushort(__float2bfloat16(b)) << 16);
}

// top-4 running-min insert (rarely-taken branch)
__device__ __forceinline__ void top4(float s, int c,
    float& b1, float& b2, float& b3, float& b4,
    int& i1, int& i2, int& i3, int& i4)
{
    if (s < b4) {
        if (s < b2) {
            b4 = b3; i4 = i3; b3 = b2; i3 = i2;
            if (s < b1) { b2 = b1; i2 = i1; b1 = s; i1 = c; }
            else        { b2 = s;  i2 = c; }
        } else {
            if (s < b3) { b4 = b3; i4 = i3; b3 = s; i3 = c; }
            else        { b4 = s;  i4 = c; }
        }
    }
}

// ---------------------------------------------------------------------------
// Generic tiled GEMM: C = act(bn(A[N,KD] @ W[KD,P] + bias))
// ---------------------------------------------------------------------------
template<int KD, int P, bool BN, bool RELU>
__global__ void __launch_bounds__(256) gemm_kernel(
    const float* __restrict__ A, const float* __restrict__ W,
    const float* __restrict__ bias,
    const float* __restrict__ gg, const float* __restrict__ be,
    const float* __restrict__ rm, const float* __restrict__ rv,
    float* __restrict__ C)
{
    __shared__ __align__(16) float As[16][68];
    __shared__ __align__(16) float Ws[16][68];
    const int tid = threadIdx.x;
    const int rid = tid >> 4, cid = tid & 15;
    const int row0 = blockIdx.y * 64, col0 = blockIdx.x * 64;
    float acc[4][4] = {};

    for (int k0 = 0; k0 < KD; k0 += 16) {
        __syncthreads();
        #pragma unroll
        for (int i = 0; i < 4; i++) {
            int idx = tid + i * 256;
            int r  = idx >> 4, kk  = idx & 15;
            As[kk][r] = A[(size_t)(row0 + r) * KD + (k0 + kk)];
            int kk2 = idx >> 6, c  = idx & 63;
            Ws[kk2][c] = W[(size_t)(k0 + kk2) * P + (col0 + c)];
        }
        __syncthreads();
        #pragma unroll
        for (int kk = 0; kk < 16; kk++) {
            float4 a = *(const float4*)&As[kk][rid * 4];
            float4 w = *(const float4*)&Ws[kk][cid * 4];
            float av[4] = {a.x, a.y, a.z, a.w};
            float wv[4] = {w.x, w.y, w.z, w.w};
            #pragma unroll
            for (int r = 0; r < 4; r++)
                #pragma unroll
                for (int c = 0; c < 4; c++)
                    acc[r][c] += av[r] * wv[c];
        }
    }
    #pragma unroll
    for (int r = 0; r < 4; r++) {
        int row = row0 + rid * 4 + r;
        #pragma unroll
        for (int c = 0; c < 4; c++) {
            int col = col0 + cid * 4 + c;
            float v = acc[r][c] + bias[col];
            if constexpr (BN)
                v = (v - rm[col]) / sqrtf(rv[col] + EPSBN) * gg[col] + be[col];
            if constexpr (RELU)
                v = fmaxf(v, 0.0f);
            C[(size_t)row * P + col] = v;
        }
    }
}

// ---------------------------------------------------------------------------
// codebook prep: ||e||^2 fp32 + bf16 hi-limb
// ---------------------------------------------------------------------------
__global__ void norm_kernel(const float* __restrict__ cbk)
{
    int i = blockIdx.x * 256 + threadIdx.x;
    const float4* p = (const float4*)(cbk + (size_t)i * DIM);
    float s = 0.f;
    #pragma unroll
    for (int j = 0; j < DIM / 4; j++) {
        float4 q = p[j];
        s += q.x * q.x + q.y * q.y + q.z * q.z + q.w * q.w;
    }
    g_nn[i] = s;
}

__global__ void split_kernel(const float* __restrict__ cbk)
{
    size_t i = (size_t)blockIdx.x * 256 + threadIdx.x;
    g_cbh[i] = __float2bfloat16(cbk[i]);
}

// ---------------------------------------------------------------------------
// Residual VQ v9: hh-only mma.sync scoring, dual accumulator chains,
//                 3-buffer cp.async pipeline (1 sync/tile),
//                 top-4/thread capture + exact fp32 rescore.
//  CTA: 64 rows, 8 warps. warp = rowgroup(16 rows) x code-half(64 of 128-tile).
//  Rescore reproduces reference rounding: d = (rr - 2*dot_fp32) + ee.
// ---------------------------------------------------------------------------
#define VROWS 64
#define TC    128
#define NT    (KCODES / TC)
#define RES_STRIDE 132
#define EBUF_B (TC * 256)                  // 32768 bytes per buffer

// smem byte offsets
#define SM_RES  0                          // 64*132*4 = 33792
#define SM_RRS  33792                      // 64 floats
#define SM_CAND 34048                      // 64*32 ints = 8192
#define SM_BIDX 42240                      // 64 ints
#define SM_EBUF 42496                      // 3 * EBUF_B
#define SM_TOTAL (SM_EBUF + 3 * EBUF_B)    // 140800

__device__ __forceinline__ void stageE(uint32_t ebuf_sm,
                                       const __nv_bfloat16* __restrict__ bh,
                                       int tile, int tid)
{
    #pragma unroll
    for (int i = 0; i < 8; i++) {
        int ch = tid + i * 256;                   // 0..2047
        int code = ch >> 4, g = ch & 15;
        const __nv_bfloat16* src = bh + ((size_t)(tile * TC + code) << 7) + (g << 3);
        uint32_t dst = ebuf_sm + code * 256 + ((g ^ (code & 7)) << 4);
        asm volatile("cp.async.cg.shared.global [%0], [%1], 16;"
                     :: "r"(dst), "l"(src));
    }
    asm volatile("cp.async.commit_group;");
}

__global__ void __launch_bounds__(256, 1) vq_kernel(
    const float* __restrict__ ze, const float* __restrict__ cbk,
    float* __restrict__ out)
{
    extern __shared__ char smc[];
    float* res     = (float*)(smc + SM_RES);
    float* rr_s    = (float*)(smc + SM_RRS);
    int*   cand    = (int*)(smc + SM_CAND);
    int*   bestIdx = (int*)(smc + SM_BIDX);
    const uint32_t sb_ebuf = smem_u32(smc + SM_EBUF);

    const int tid  = threadIdx.x;
    const int warp = tid >> 5, lane = tid & 31;
    const int row0 = blockIdx.x * VROWS;
    const int rg   = warp >> 1;                 // rowgroup (16 rows)
    const int chf  = warp & 1;                  // code half within tile (64)
    const int tig  = lane & 3, gid = lane >> 2;
    const int r_lo = rg * 16 + gid, r_hi = r_lo + 8;
    const int codeL = chf * 64 + (lane & 7);    // smem code row base this lane reads
    const int grnb  = lane >> 3;                // 0..3 (x4 block id)
    const int cs    = lane & 7;                 // swizzle key (codeL & 7)

    // residual := ze
    #pragma unroll
    for (int i = 0; i < 8; i++) {
        int g = tid + i * 256;
        int r = g >> 5, dq = g & 31;
        *(float4*)(res + r * RES_STRIDE + dq * 4) =
            *(const float4*)(ze + (size_t)(row0 + r) * DIM + dq * 4);
    }
    __syncthreads();

    for (int m = 0; m < MBOOK; m++) {
        const float* Eb = cbk + (size_t)m * KCODES * DIM;
        const float* nb = g_nn + m * KCODES;
        const __nv_bfloat16* bh = g_cbh + (size_t)m * KCODES * DIM;

        // prime the 3-stage pipeline: tiles 0 and 1
        stageE(sb_ebuf, bh, 0, tid);
        stageE(sb_ebuf + EBUF_B, bh, 1, tid);

        // emit res_s[m]
        {
            size_t ob = RES_OFF + (size_t)m * NROWS * DIM + (size_t)row0 * DIM;
            #pragma unroll
            for (int i = 0; i < 8; i++) {
                int g = tid + i * 256;
                int r = g >> 5, dq = g & 31;
                *(float4*)(out + ob + (size_t)r * DIM + dq * 4) =
                    *(const float4*)(res + r * RES_STRIDE + dq * 4);
            }
        }

        // per-row ||r||^2 (sequential dim order)
        if (tid < VROWS) {
            float s = 0.f;
            #pragma unroll
            for (int dq = 0; dq < 32; dq++) {
                float4 v = *(const float4*)(res + tid * RES_STRIDE + dq * 4);
                s = fmaf(v.x, v.x, s); s = fmaf(v.y, v.y, s);
                s = fmaf(v.z, v.z, s); s = fmaf(v.w, v.w, s);
            }
            rr_s[tid] = s;
        }
        __syncthreads();

        const float rr_lo = rr_s[r_lo], rr_hi = rr_s[r_hi];

        // build A hi-limb fragments in registers from res smem
        uint32_t Ah[8][4];
        #pragma unroll
        for (int ks = 0; ks < 8; ks++) {
            int c0 = ks * 16 + 2 * tig;
            const float* pl = res + r_lo * RES_STRIDE + c0;
            const float* ph = res + r_hi * RES_STRIDE + c0;
            Ah[ks][0] = pack_bf16f(pl[0], pl[1]);
            Ah[ks][1] = pack_bf16f(ph[0], ph[1]);
            Ah[ks][2] = pack_bf16f(pl[8], pl[9]);
            Ah[ks][3] = pack_bf16f(ph[8], ph[9]);
        }

        // top-4 approx candidates per thread for each of its 2 rows
        float b1l = FLT_MAX, b2l = FLT_MAX, b3l = FLT_MAX, b4l = FLT_MAX;
        float b1h = FLT_MAX, b2h = FLT_MAX, b3h = FLT_MAX, b4h = FLT_MAX;
        int   i1l = 0x7fffffff, i2l = 0x7fffffff, i3l = 0x7fffffff, i4l = 0x7fffffff;
        int   i1h = 0x7fffffff, i2h = 0x7fffffff, i3h = 0x7fffffff, i4h = 0x7fffffff;

        for (int t = 0; t < NT; t++) {
            // wait for tile t's staging group (groups complete in commit order)
            if (t < NT - 1) asm volatile("cp.async.wait_group 1;");
            else            asm volatile("cp.async.wait_group 0;");
            __syncthreads();                    // single barrier per tile

            // stage tile t+2 into the buffer freed at tile t-1 (safe: all
            // threads passed the barrier above, i.e. finished tile t-1)
            if (t + 2 < NT)
                stageE(sb_ebuf + ((t + 2) % 3) * EBUF_B, bh, t + 2, tid);

            const uint32_t ebuf = sb_ebuf + (t % 3) * EBUF_B;
            const int tbase = t * TC + chf * 64;

            #pragma unroll
            for (int ng = 0; ng < 8; ng++) {
                const uint32_t rowa = ebuf + (codeL + ng * 8) * 256;
                // two independent accumulator chains (even/odd kstep)
                float d0 = 0.f, d1 = 0.f, d2 = 0.f, d3 = 0.f;
                float e0 = 0.f, e1 = 0.f, e2 = 0.f, e3 = 0.f;

                #pragma unroll
                for (int kp = 0; kp < 4; kp++) {
                    uint32_t goff = (uint32_t)(((kp * 4 + grnb) ^ cs) << 4);
                    uint32_t h0, h1, h2, h3;
                    LDSM4(h0, h1, h2, h3, rowa + goff);
                    const int ke = kp * 2, ko = ke + 1;
                    MMA16816(d0,d1,d2,d3, Ah[ke][0],Ah[ke][1],Ah[ke][2],Ah[ke][3], h0,h1);
                    MMA16816(e0,e1,e2,e3, Ah[ko][0],Ah[ko][1],Ah[ko][2],Ah[ko][3], h2,h3);
                }

                // fold chains; approx scores for codes (cA,cA+1) x rows
                const int cA = tbase + ng * 8 + 2 * tig;
                const float eeA = __ldg(nb + cA), eeB = __ldg(nb + cA + 1);
                top4(fmaf(-2.0f, d0 + e0, rr_lo) + eeA, cA,     b1l,b2l,b3l,b4l, i1l,i2l,i3l,i4l);
                top4(fmaf(-2.0f, d1 + e1, rr_lo) + eeB, cA + 1, b1l,b2l,b3l,b4l, i1l,i2l,i3l,i4l);
                top4(fmaf(-2.0f, d2 + e2, rr_hi) + eeA, cA,     b1h,b2h,b3h,b4h, i1h,i2h,i3h,i4h);
                top4(fmaf(-2.0f, d3 + e3, rr_hi) + eeB, cA + 1, b1h,b2h,b3h,b4h, i1h,i2h,i3h,i4h);
            }
        }
        __syncthreads();

        // deposit candidates: 8 threads/row x 4 = 32 slots/row
        {
            int slot = (chf * 4 + tig) * 4;
            cand[r_lo * 32 + slot]     = i1l;
            cand[r_lo * 32 + slot + 1] = i2l;
            cand[r_lo * 32 + slot + 2] = i3l;
            cand[r_lo * 32 + slot + 3] = i4l;
            cand[r_hi * 32 + slot]     = i1h;
            cand[r_hi * 32 + slot + 1] = i2h;
            cand[r_hi * 32 + slot + 2] = i3h;
            cand[r_hi * 32 + slot + 3] = i4h;
        }
        __syncthreads();

        // exact fp32 rescore of the 32 candidates per row (reference rounding)
        #pragma unroll 1
        for (int rw = 0; rw < VROWS / 8; rw++) {
            int row = warp * 8 + rw;
            int c = cand[row * 32 + lane];
            const float4* e  = (const float4*)(Eb + (size_t)c * DIM);
            const float4* rp = (const float4*)(res + row * RES_STRIDE);
            float p = 0.f;
            #pragma unroll
            for (int i = 0; i < 32; i++) {
                float4 rv = rp[i];
                float4 ev = __ldg(e + i);
                p = fmaf(rv.x, ev.x, p); p = fmaf(rv.y, ev.y, p);
                p = fmaf(rv.z, ev.z, p); p = fmaf(rv.w, ev.w, p);
            }
            float dd = fmaf(-2.0f, p, rr_s[row]) + __ldg(nb + c);
            float bv = dd; int bi = c;
            #pragma unroll
            for (int off = 16; off >= 1; off >>= 1) {
                float ov = __shfl_down_sync(0xffffffffu, bv, off);
                int   oi = __shfl_down_sync(0xffffffffu, bi, off);
                if (ov < bv || (ov == bv && oi < bi)) { bv = ov; bi = oi; }
            }
            if (lane == 0) bestIdx[row] = bi;
        }
        __syncthreads();

        // quantize: emit ce_s[m], residual -= ce (fp32 codebook, exact)
        #pragma unroll 1
        for (int rw = 0; rw < VROWS / 8; rw++) {
            int row = warp * 8 + rw;
            int idx = bestIdx[row];
            float4 cv = __ldg((const float4*)(Eb + (size_t)idx * DIM) + lane);
            size_t ob = CE_OFF + (size_t)m * NROWS * DIM
                      + (size_t)(row0 + row) * DIM;
            *(float4*)(out + ob + lane * 4) = cv;
            float4* rp = (float4*)(res + row * RES_STRIDE + lane * 4);
            float4 rv = *rp;
            rv.x -= cv.x; rv.y -= cv.y; rv.z -= cv.z; rv.w -= cv.w;
            *rp = rv;
        }
        __syncthreads();
    }
}

// ---------------------------------------------------------------------------
// di = ze + (sum_m ce_s[m] - ze)
// ---------------------------------------------------------------------------
__global__ void di_kernel(const float* __restrict__ out)
{
    int i = blockIdx.x * 256 + threadIdx.x;
    float zev = g_ze[i];
    float zq = 0.f;
    #pragma unroll
    for (int m = 0; m < MBOOK; m++)
        zq += out[CE_OFF + (size_t)m * NROWS * DIM + i];
    g_di[i] = zev + (zq - zev);
}

// ---------------------------------------------------------------------------
extern "C" void kernel_launch(void* const* d_in, const int* in_sizes, int n_in,
                              void* d_out, int out_size)
{
    const float* x   = (const float*)d_in[0];
    const float* W1  = (const float*)d_in[1];
    const float* b1  = (const float*)d_in[2];
    const float* g1  = (const float*)d_in[3];
    const float* be1 = (const float*)d_in[4];
    const float* rm1 = (const float*)d_in[5];
    const float* rv1 = (const float*)d_in[6];
    const float* W2  = (const float*)d_in[7];
    const float* b2  = (const float*)d_in[8];
    const float* g2  = (const float*)d_in[9];
    const float* be2 = (const float*)d_in[10];
    const float* rm2 = (const float*)d_in[11];
    const float* rv2 = (const float*)d_in[12];
    const float* W3  = (const float*)d_in[13];
    const float* b3  = (const float*)d_in[14];
    const float* cbk = (const float*)d_in[15];
    const float* W4  = (const float*)d_in[16];
    const float* b4  = (const float*)d_in[17];
    const float* g3  = (const float*)d_in[18];
    const float* be3 = (const float*)d_in[19];
    const float* rm3 = (const float*)d_in[20];
    const float* rv3 = (const float*)d_in[21];
    const float* W5  = (const float*)d_in[22];
    const float* b5  = (const float*)d_in[23];
    const float* g4  = (const float*)d_in[24];
    const float* be4 = (const float*)d_in[25];
    const float* rm4 = (const float*)d_in[26];
    const float* rv4 = (const float*)d_in[27];
    const float* W6  = (const float*)d_in[28];
    const float* b6  = (const float*)d_in[29];
    float* out = (float*)d_out;

    float *h1, *h2, *ze, *di, *t1, *t2;
    cudaGetSymbolAddress((void**)&h1, g_h1);
    cudaGetSymbolAddress((void**)&h2, g_h2);
    cudaGetSymbolAddress((void**)&ze, g_ze);
    cudaGetSymbolAddress((void**)&di, g_di);
    cudaGetSymbolAddress((void**)&t1, g_t1);
    cudaGetSymbolAddress((void**)&t2, g_t2);

    cudaFuncSetAttribute(vq_kernel,
                         cudaFuncAttributeMaxDynamicSharedMemorySize, SM_TOTAL);

    // codebook prep (launches 0,1)
    norm_kernel<<<MBOOK * KCODES / 256, 256>>>(cbk);
    split_kernel<<<MBOOK * KCODES * DIM / 256, 256>>>(cbk);

    // encoder (launches 2,3,4)
    gemm_kernel<256, 128, true,  true ><<<dim3(2, 128), 256>>>(x,  W1, b1, g1, be1, rm1, rv1, h1);
    gemm_kernel<128, 256, true,  true ><<<dim3(4, 128), 256>>>(h1, W2, b2, g2, be2, rm2, rv2, h2);
    gemm_kernel<256, 128, false, false><<<dim3(2, 128), 256>>>(h2, W3, b3, nullptr, nullptr, nullptr, nullptr, ze);

    // residual VQ (launch 5)
    vq_kernel<<<NROWS / VROWS, 256, SM_TOTAL>>>(ze, cbk, out);

    // straight-through: di = ze + (zq - ze)
    di_kernel<<<NROWS * DIM / 256, 256>>>(out);

    // decoder
    gemm_kernel<128, 256, true,  true ><<<dim3(4, 128), 256>>>(di, W4, b4, g3, be3, rm3, rv3, t1);
    gemm_kernel<256, 128, true,  true ><<<dim3(2, 128), 256>>>(t1, W5, b5, g4, be4, rm4, rv4, t2);
    gemm_kernel<128, 256, false, false><<<dim3(4, 128), 256>>>(t2, W6, b6, nullptr, nullptr, nullptr, nullptr, out);
}

// round 10
// speedup vs baseline: 4.7918x; 1.3603x over previous
#include <cuda_runtime.h>
#include <cuda_bf16.h>
#include <math.h>
#include <float.h>
#include <stdint.h>

#define NROWS   8192
#define IN_DIM  256
#define DIM     128
#define KCODES  8192
#define MBOOK   8
#define EPSBN   1e-5f

// output layout: x_hat [8192,256] ++ res_s [8,8192,128] ++ ce_s [8,8192,128]
#define RES_OFF ((size_t)NROWS * IN_DIM)
#define CE_OFF  (RES_OFF + (size_t)MBOOK * NROWS * DIM)

// scratch (static device allocations only)
__device__ float g_h1[NROWS * 128];
__device__ float g_h2[NROWS * 256];
__device__ float g_ze[NROWS * DIM];
__device__ float g_di[NROWS * DIM];
__device__ float g_t1[NROWS * 256];
__device__ float g_t2[NROWS * 128];
__device__ float g_nn[MBOOK * KCODES];                 // ||e||^2 fp32
__device__ __nv_bfloat16 g_cbh[MBOOK * KCODES * DIM];  // bf16 hi limb of E

// ---------------------------------------------------------------------------
// mma.sync / ldmatrix helpers (baseline PTX, compiles for compute_103)
// ---------------------------------------------------------------------------
#define MMA16816(d0,d1,d2,d3,a0,a1,a2,a3,b0,b1) \
    asm volatile("mma.sync.aligned.m16n8k16.row.col.f32.bf16.bf16.f32 " \
        "{%0,%1,%2,%3}, {%4,%5,%6,%7}, {%8,%9}, {%0,%1,%2,%3};" \
        : "+f"(d0), "+f"(d1), "+f"(d2), "+f"(d3) \
        : "r"(a0), "r"(a1), "r"(a2), "r"(a3), "r"(b0), "r"(b1))

#define LDSM4(r0,r1,r2,r3,addr) \
    asm volatile("ldmatrix.sync.aligned.m8n8.x4.shared.b16 {%0,%1,%2,%3}, [%4];" \
        : "=r"(r0), "=r"(r1), "=r"(r2), "=r"(r3) : "r"(addr))

__device__ __forceinline__ uint32_t smem_u32(const void* p) {
    uint32_t a;
    asm("{ .reg .u64 t; cvta.to.shared.u64 t, %1; cvt.u32.u64 %0, t; }"
        : "=r"(a) : "l"(p));
    return a;
}

__device__ __forceinline__ uint32_t pack_bf16f(float a, float b) {
    return (uint32_t)__bfloat16_as_ushort(__float2bfloat16(a))
         | ((uint32_t)__bfloat16_as_ushort(__float2bfloat16(b)) << 16);
}

// top-2 running-min insert
__device__ __forceinline__ void top2(float s, int c,
    float& b1, float& b2, int& i1, int& i2)
{
    if (s < b2) {
        if (s < b1) { b2 = b1; i2 = i1; b1 = s; i1 = c; }
        else        { b2 = s;  i2 = c; }
    }
}

// ---------------------------------------------------------------------------
// Generic tiled GEMM: C = act(bn(A[N,KD] @ W[KD,P] + bias))
// ---------------------------------------------------------------------------
template<int KD, int P, bool BN, bool RELU>
__global__ void __launch_bounds__(256) gemm_kernel(
    const float* __restrict__ A, const float* __restrict__ W,
    const float* __restrict__ bias,
    const float* __restrict__ gg, const float* __restrict__ be,
    const float* __restrict__ rm, const float* __restrict__ rv,
    float* __restrict__ C)
{
    __shared__ __align__(16) float As[16][68];
    __shared__ __align__(16) float Ws[16][68];
    const int tid = threadIdx.x;
    const int rid = tid >> 4, cid = tid & 15;
    const int row0 = blockIdx.y * 64, col0 = blockIdx.x * 64;
    float acc[4][4] = {};

    for (int k0 = 0; k0 < KD; k0 += 16) {
        __syncthreads();
        #pragma unroll
        for (int i = 0; i < 4; i++) {
            int idx = tid + i * 256;
            int r  = idx >> 4, kk  = idx & 15;
            As[kk][r] = A[(size_t)(row0 + r) * KD + (k0 + kk)];
            int kk2 = idx >> 6, c  = idx & 63;
            Ws[kk2][c] = W[(size_t)(k0 + kk2) * P + (col0 + c)];
        }
        __syncthreads();
        #pragma unroll
        for (int kk = 0; kk < 16; kk++) {
            float4 a = *(const float4*)&As[kk][rid * 4];
            float4 w = *(const float4*)&Ws[kk][cid * 4];
            float av[4] = {a.x, a.y, a.z, a.w};
            float wv[4] = {w.x, w.y, w.z, w.w};
            #pragma unroll
            for (int r = 0; r < 4; r++)
                #pragma unroll
                for (int c = 0; c < 4; c++)
                    acc[r][c] += av[r] * wv[c];
        }
    }
    #pragma unroll
    for (int r = 0; r < 4; r++) {
        int row = row0 + rid * 4 + r;
        #pragma unroll
        for (int c = 0; c < 4; c++) {
            int col = col0 + cid * 4 + c;
            float v = acc[r][c] + bias[col];
            if constexpr (BN)
                v = (v - rm[col]) / sqrtf(rv[col] + EPSBN) * gg[col] + be[col];
            if constexpr (RELU)
                v = fmaxf(v, 0.0f);
            C[(size_t)row * P + col] = v;
        }
    }
}

// ---------------------------------------------------------------------------
// codebook prep: ||e||^2 fp32 + bf16 hi-limb
// ---------------------------------------------------------------------------
__global__ void norm_kernel(const float* __restrict__ cbk)
{
    int i = blockIdx.x * 256 + threadIdx.x;
    const float4* p = (const float4*)(cbk + (size_t)i * DIM);
    float s = 0.f;
    #pragma unroll
    for (int j = 0; j < DIM / 4; j++) {
        float4 q = p[j];
        s += q.x * q.x + q.y * q.y + q.z * q.z + q.w * q.w;
    }
    g_nn[i] = s;
}

__global__ void split_kernel(const float* __restrict__ cbk)
{
    size_t i = (size_t)blockIdx.x * 256 + threadIdx.x;
    g_cbh[i] = __float2bfloat16(cbk[i]);
}

// ---------------------------------------------------------------------------
// Residual VQ v10: hh-only mma.sync scoring, 2 CTAs/SM (32 rows/CTA),
//                  2-buffer cp.async pipeline (1 sync/tile),
//                  top-2/thread capture (32 cands/row) + exact fp32 rescore.
//  CTA: 32 rows, 8 warps. warp = rowgroup(16 rows) x code-quarter(32 of 128).
//  Rescore reproduces reference rounding: d = (rr - 2*dot_fp32) + ee.
// ---------------------------------------------------------------------------
#define VROWS 32
#define TC    128
#define NT    (KCODES / TC)
#define RES_STRIDE 132
#define EBUF_B (TC * 256)                  // 32768 bytes per buffer

// smem byte offsets
#define SM_RES  0                          // 32*132*4 = 16896
#define SM_RRS  16896                      // 32 floats (pad to 128)
#define SM_CAND 17024                      // 32*32 ints = 4096
#define SM_BIDX 21120                      // 32 ints (pad to 128)
#define SM_EBUF 21248                      // 2 * EBUF_B
#define SM_TOTAL (SM_EBUF + 2 * EBUF_B)    // 86784

__device__ __forceinline__ void stageE(uint32_t ebuf_sm,
                                       const __nv_bfloat16* __restrict__ bh,
                                       int tile, int tid)
{
    #pragma unroll
    for (int i = 0; i < 8; i++) {
        int ch = tid + i * 256;                   // 0..2047
        int code = ch >> 4, g = ch & 15;
        const __nv_bfloat16* src = bh + ((size_t)(tile * TC + code) << 7) + (g << 3);
        uint32_t dst = ebuf_sm + code * 256 + ((g ^ (code & 7)) << 4);
        asm volatile("cp.async.cg.shared.global [%0], [%1], 16;"
                     :: "r"(dst), "l"(src));
    }
    asm volatile("cp.async.commit_group;");
}

__global__ void __launch_bounds__(256, 2) vq_kernel(
    const float* __restrict__ ze, const float* __restrict__ cbk,
    float* __restrict__ out)
{
    extern __shared__ char smc[];
    float* res     = (float*)(smc + SM_RES);
    float* rr_s    = (float*)(smc + SM_RRS);
    int*   cand    = (int*)(smc + SM_CAND);
    int*   bestIdx = (int*)(smc + SM_BIDX);
    const uint32_t sb_ebuf = smem_u32(smc + SM_EBUF);

    const int tid  = threadIdx.x;
    const int warp = tid >> 5, lane = tid & 31;
    const int row0 = blockIdx.x * VROWS;
    const int rg   = warp >> 2;                 // rowgroup (16 rows)
    const int chf  = warp & 3;                  // code quarter within tile (32)
    const int tig  = lane & 3, gid = lane >> 2;
    const int r_lo = rg * 16 + gid, r_hi = r_lo + 8;
    const int codeL = chf * 32 + (lane & 7);    // smem code row base this lane reads
    const int grnb  = lane >> 3;                // 0..3 (x4 block id)
    const int cs    = lane & 7;                 // swizzle key (codeL & 7)

    // residual := ze  (32 rows x 128 dims = 1024 float4)
    #pragma unroll
    for (int i = 0; i < 4; i++) {
        int g = tid + i * 256;
        int r = g >> 5, dq = g & 31;
        *(float4*)(res + r * RES_STRIDE + dq * 4) =
            *(const float4*)(ze + (size_t)(row0 + r) * DIM + dq * 4);
    }
    __syncthreads();

    for (int m = 0; m < MBOOK; m++) {
        const float* Eb = cbk + (size_t)m * KCODES * DIM;
        const float* nb = g_nn + m * KCODES;
        const __nv_bfloat16* bh = g_cbh + (size_t)m * KCODES * DIM;

        // prime the pipeline: tile 0
        stageE(sb_ebuf, bh, 0, tid);

        // emit res_s[m]
        {
            size_t ob = RES_OFF + (size_t)m * NROWS * DIM + (size_t)row0 * DIM;
            #pragma unroll
            for (int i = 0; i < 4; i++) {
                int g = tid + i * 256;
                int r = g >> 5, dq = g & 31;
                *(float4*)(out + ob + (size_t)r * DIM + dq * 4) =
                    *(const float4*)(res + r * RES_STRIDE + dq * 4);
            }
        }

        // per-row ||r||^2 (sequential dim order)
        if (tid < VROWS) {
            float s = 0.f;
            #pragma unroll
            for (int dq = 0; dq < 32; dq++) {
                float4 v = *(const float4*)(res + tid * RES_STRIDE + dq * 4);
                s = fmaf(v.x, v.x, s); s = fmaf(v.y, v.y, s);
                s = fmaf(v.z, v.z, s); s = fmaf(v.w, v.w, s);
            }
            rr_s[tid] = s;
        }
        __syncthreads();

        const float rr_lo = rr_s[r_lo], rr_hi = rr_s[r_hi];

        // build A hi-limb fragments in registers from res smem
        uint32_t Ah[8][4];
        #pragma unroll
        for (int ks = 0; ks < 8; ks++) {
            int c0 = ks * 16 + 2 * tig;
            const float* pl = res + r_lo * RES_STRIDE + c0;
            const float* ph = res + r_hi * RES_STRIDE + c0;
            Ah[ks][0] = pack_bf16f(pl[0], pl[1]);
            Ah[ks][1] = pack_bf16f(ph[0], ph[1]);
            Ah[ks][2] = pack_bf16f(pl[8], pl[9]);
            Ah[ks][3] = pack_bf16f(ph[8], ph[9]);
        }

        // top-2 approx candidates per thread for each of its 2 rows
        float b1l = FLT_MAX, b2l = FLT_MAX, b1h = FLT_MAX, b2h = FLT_MAX;
        int   i1l = 0x7fffffff, i2l = 0x7fffffff;
        int   i1h = 0x7fffffff, i2h = 0x7fffffff;

        for (int t = 0; t < NT; t++) {
            // wait for tile t's staging, make visible, then prefetch t+1
            asm volatile("cp.async.wait_group 0;");
            __syncthreads();                    // single barrier per tile
            if (t + 1 < NT)
                stageE(sb_ebuf + ((t + 1) & 1) * EBUF_B, bh, t + 1, tid);

            const uint32_t ebuf = sb_ebuf + (t & 1) * EBUF_B;
            const int tbase = t * TC + chf * 32;

            #pragma unroll
            for (int ng = 0; ng < 4; ng++) {
                const uint32_t rowa = ebuf + (codeL + ng * 8) * 256;
                // two independent accumulator chains (even/odd kstep)
                float d0 = 0.f, d1 = 0.f, d2 = 0.f, d3 = 0.f;
                float e0 = 0.f, e1 = 0.f, e2 = 0.f, e3 = 0.f;

                #pragma unroll
                for (int kp = 0; kp < 4; kp++) {
                    uint32_t goff = (uint32_t)(((kp * 4 + grnb) ^ cs) << 4);
                    uint32_t h0, h1, h2, h3;
                    LDSM4(h0, h1, h2, h3, rowa + goff);
                    const int ke = kp * 2, ko = ke + 1;
                    MMA16816(d0,d1,d2,d3, Ah[ke][0],Ah[ke][1],Ah[ke][2],Ah[ke][3], h0,h1);
                    MMA16816(e0,e1,e2,e3, Ah[ko][0],Ah[ko][1],Ah[ko][2],Ah[ko][3], h2,h3);
                }

                // fold chains; approx scores for codes (cA,cA+1) x rows
                const int cA = tbase + ng * 8 + 2 * tig;
                const float eeA = __ldg(nb + cA), eeB = __ldg(nb + cA + 1);
                top2(fmaf(-2.0f, d0 + e0, rr_lo) + eeA, cA,     b1l,b2l, i1l,i2l);
                top2(fmaf(-2.0f, d1 + e1, rr_lo) + eeB, cA + 1, b1l,b2l, i1l,i2l);
                top2(fmaf(-2.0f, d2 + e2, rr_hi) + eeA, cA,     b1h,b2h, i1h,i2h);
                top2(fmaf(-2.0f, d3 + e3, rr_hi) + eeB, cA + 1, b1h,b2h, i1h,i2h);
            }
        }
        __syncthreads();

        // deposit candidates: 16 threads/row x 2 = 32 slots/row
        {
            int slot = (chf * 4 + tig) * 2;
            cand[r_lo * 32 + slot]     = i1l;
            cand[r_lo * 32 + slot + 1] = i2l;
            cand[r_hi * 32 + slot]     = i1h;
            cand[r_hi * 32 + slot + 1] = i2h;
        }
        __syncthreads();

        // exact fp32 rescore of the 32 candidates per row (reference rounding)
        #pragma unroll 1
        for (int rw = 0; rw < VROWS / 8; rw++) {
            int row = warp * 4 + rw;
            int c = cand[row * 32 + lane];
            const float4* e  = (const float4*)(Eb + (size_t)c * DIM);
            const float4* rp = (const float4*)(res + row * RES_STRIDE);
            float p = 0.f;
            #pragma unroll
            for (int i = 0; i < 32; i++) {
                float4 rv = rp[i];
                float4 ev = __ldg(e + i);
                p = fmaf(rv.x, ev.x, p); p = fmaf(rv.y, ev.y, p);
                p = fmaf(rv.z, ev.z, p); p = fmaf(rv.w, ev.w, p);
            }
            float dd = fmaf(-2.0f, p, rr_s[row]) + __ldg(nb + c);
            float bv = dd; int bi = c;
            #pragma unroll
            for (int off = 16; off >= 1; off >>= 1) {
                float ov = __shfl_down_sync(0xffffffffu, bv, off);
                int   oi = __shfl_down_sync(0xffffffffu, bi, off);
                if (ov < bv || (ov == bv && oi < bi)) { bv = ov; bi = oi; }
            }
            if (lane == 0) bestIdx[row] = bi;
        }
        __syncthreads();

        // quantize: emit ce_s[m], residual -= ce (fp32 codebook, exact)
        #pragma unroll 1
        for (int rw = 0; rw < VROWS / 8; rw++) {
            int row = warp * 4 + rw;
            int idx = bestIdx[row];
            float4 cv = __ldg((const float4*)(Eb + (size_t)idx * DIM) + lane);
            size_t ob = CE_OFF + (size_t)m * NROWS * DIM
                      + (size_t)(row0 + row) * DIM;
            *(float4*)(out + ob + lane * 4) = cv;
            float4* rp = (float4*)(res + row * RES_STRIDE + lane * 4);
            float4 rv = *rp;
            rv.x -= cv.x; rv.y -= cv.y; rv.z -= cv.z; rv.w -= cv.w;
            *rp = rv;
        }
        __syncthreads();
    }
}

// ---------------------------------------------------------------------------
// di = ze + (sum_m ce_s[m] - ze)
// ---------------------------------------------------------------------------
__global__ void di_kernel(const float* __restrict__ out)
{
    int i = blockIdx.x * 256 + threadIdx.x;
    float zev = g_ze[i];
    float zq = 0.f;
    #pragma unroll
    for (int m = 0; m < MBOOK; m++)
        zq += out[CE_OFF + (size_t)m * NROWS * DIM + i];
    g_di[i] = zev + (zq - zev);
}

// ---------------------------------------------------------------------------
extern "C" void kernel_launch(void* const* d_in, const int* in_sizes, int n_in,
                              void* d_out, int out_size)
{
    const float* x   = (const float*)d_in[0];
    const float* W1  = (const float*)d_in[1];
    const float* b1  = (const float*)d_in[2];
    const float* g1  = (const float*)d_in[3];
    const float* be1 = (const float*)d_in[4];
    const float* rm1 = (const float*)d_in[5];
    const float* rv1 = (const float*)d_in[6];
    const float* W2  = (const float*)d_in[7];
    const float* b2  = (const float*)d_in[8];
    const float* g2  = (const float*)d_in[9];
    const float* be2 = (const float*)d_in[10];
    const float* rm2 = (const float*)d_in[11];
    const float* rv2 = (const float*)d_in[12];
    const float* W3  = (const float*)d_in[13];
    const float* b3  = (const float*)d_in[14];
    const float* cbk = (const float*)d_in[15];
    const float* W4  = (const float*)d_in[16];
    const float* b4  = (const float*)d_in[17];
    const float* g3  = (const float*)d_in[18];
    const float* be3 = (const float*)d_in[19];
    const float* rm3 = (const float*)d_in[20];
    const float* rv3 = (const float*)d_in[21];
    const float* W5  = (const float*)d_in[22];
    const float* b5  = (const float*)d_in[23];
    const float* g4  = (const float*)d_in[24];
    const float* be4 = (const float*)d_in[25];
    const float* rm4 = (const float*)d_in[26];
    const float* rv4 = (const float*)d_in[27];
    const float* W6  = (const float*)d_in[28];
    const float* b6  = (const float*)d_in[29];
    float* out = (float*)d_out;

    float *h1, *h2, *ze, *di, *t1, *t2;
    cudaGetSymbolAddress((void**)&h1, g_h1);
    cudaGetSymbolAddress((void**)&h2, g_h2);
    cudaGetSymbolAddress((void**)&ze, g_ze);
    cudaGetSymbolAddress((void**)&di, g_di);
    cudaGetSymbolAddress((void**)&t1, g_t1);
    cudaGetSymbolAddress((void**)&t2, g_t2);

    cudaFuncSetAttribute(vq_kernel,
                         cudaFuncAttributeMaxDynamicSharedMemorySize, SM_TOTAL);

    // codebook prep (launches 0,1)
    norm_kernel<<<MBOOK * KCODES / 256, 256>>>(cbk);
    split_kernel<<<MBOOK * KCODES * DIM / 256, 256>>>(cbk);

    // encoder (launches 2,3,4)
    gemm_kernel<256, 128, true,  true ><<<dim3(2, 128), 256>>>(x,  W1, b1, g1, be1, rm1, rv1, h1);
    gemm_kernel<128, 256, true,  true ><<<dim3(4, 128), 256>>>(h1, W2, b2, g2, be2, rm2, rv2, h2);
    gemm_kernel<256, 128, false, false><<<dim3(2, 128), 256>>>(h2, W3, b3, nullptr, nullptr, nullptr, nullptr, ze);

    // residual VQ (launch 5)
    vq_kernel<<<NROWS / VROWS, 256, SM_TOTAL>>>(ze, cbk, out);

    // straight-through: di = ze + (zq - ze)
    di_kernel<<<NROWS * DIM / 256, 256>>>(out);

    // decoder
    gemm_kernel<128, 256, true,  true ><<<dim3(4, 128), 256>>>(di, W4, b4, g3, be3, rm3, rv3, t1);
    gemm_kernel<256, 128, true,  true ><<<dim3(2, 128), 256>>>(t1, W5, b5, g4, be4, rm4, rv4, t2);
    gemm_kernel<128, 256, false, false><<<dim3(4, 128), 256>>>(t2, W6, b6, nullptr, nullptr, nullptr, nullptr, out);
}